// round 12
// baseline (speedup 1.0000x reference)
#include <cuda_runtime.h>
#include <cuda_bf16.h>
#include <cstdint>

// Problem constants
#define BB   2
#define LL   2048
#define HH   16
#define DD   64
#define EE   1024
#define MM   (BB * LL)      /* 4096 rows */
#define QB   128
#define KVB  64

// GEMM smem geometry (fused): 4 tiles (AH,AL,BH,BL) of 128 rows x 128 B,
// XOR-swizzled, per stage. 3 stages.
#define GTILB   16384                  /* 128*128 */
#define GSTGB   (4 * GTILB)            /* 65536 */
#define GSMEM   (3 * GSTGB)            /* 196608 */

// Attention smem geometry (unchanged, validated)
#define APITCH  144
#define AKTILE  (64 * APITCH)
#define ASTAGE  (4 * AKTILE)
#define AQBYTES (2 * 128 * APITCH)
#define ASMEM   (AQBYTES + 2 * ASTAGE)

// ---------------------------------------------------------------------------
// Scratch (device globals — no runtime allocation allowed)
// ---------------------------------------------------------------------------
__device__ __nv_bfloat16 g_xhi[(size_t)MM * EE];
__device__ __nv_bfloat16 g_xlo[(size_t)MM * EE];
__device__ __nv_bfloat16 g_wqhi[(size_t)3 * EE * EE];
__device__ __nv_bfloat16 g_wqlo[(size_t)3 * EE * EE];
__device__ __nv_bfloat16 g_wohi[(size_t)EE * EE];
__device__ __nv_bfloat16 g_wolo[(size_t)EE * EE];
__device__ __nv_bfloat16 g_qkvhi[(size_t)MM * 3 * EE];
__device__ __nv_bfloat16 g_qkvlo[(size_t)MM * 3 * EE];
__device__ __nv_bfloat16 g_ahi[(size_t)MM * EE];
__device__ __nv_bfloat16 g_alo[(size_t)MM * EE];

// ---------------------------------------------------------------------------
// PTX helpers (baseline ISA only)
// ---------------------------------------------------------------------------
__device__ __forceinline__ uint32_t smem_u32(const void* p) {
    uint32_t a;
    asm("{ .reg .u64 t; cvta.to.shared.u64 t, %1; cvt.u32.u64 %0, t; }"
        : "=r"(a) : "l"(p));
    return a;
}
__device__ __forceinline__ void cp16(uint32_t saddr, const void* gaddr) {
    asm volatile("cp.async.cg.shared.global [%0], [%1], 16;"
                 :: "r"(saddr), "l"(gaddr) : "memory");
}
__device__ __forceinline__ void cp_commit() {
    asm volatile("cp.async.commit_group;" ::: "memory");
}
__device__ __forceinline__ void cp_wait1() {
    asm volatile("cp.async.wait_group 1;" ::: "memory");
}
__device__ __forceinline__ void cp_wait0() {
    asm volatile("cp.async.wait_group 0;" ::: "memory");
}
__device__ __forceinline__ void ldm4(uint32_t addr, uint32_t* r) {
    asm volatile("ldmatrix.sync.aligned.m8n8.x4.shared.b16 {%0,%1,%2,%3}, [%4];"
                 : "=r"(r[0]), "=r"(r[1]), "=r"(r[2]), "=r"(r[3]) : "r"(addr));
}
__device__ __forceinline__ void ldm4t(uint32_t addr, uint32_t* r) {
    asm volatile("ldmatrix.sync.aligned.m8n8.x4.trans.shared.b16 {%0,%1,%2,%3}, [%4];"
                 : "=r"(r[0]), "=r"(r[1]), "=r"(r[2]), "=r"(r[3]) : "r"(addr));
}
__device__ __forceinline__ void mma_bf16(float* c, const uint32_t* a,
                                         uint32_t b0, uint32_t b1) {
    asm volatile(
        "mma.sync.aligned.m16n8k16.row.col.f32.bf16.bf16.f32 "
        "{%0,%1,%2,%3}, {%4,%5,%6,%7}, {%8,%9}, {%0,%1,%2,%3};"
        : "+f"(c[0]), "+f"(c[1]), "+f"(c[2]), "+f"(c[3])
        : "r"(a[0]), "r"(a[1]), "r"(a[2]), "r"(a[3]), "r"(b0), "r"(b1));
}
__device__ __forceinline__ uint32_t pack2bf(__nv_bfloat16 x, __nv_bfloat16 y) {
    return (uint32_t)__bfloat16_as_ushort(x) |
           ((uint32_t)__bfloat16_as_ushort(y) << 16);
}

// ---------------------------------------------------------------------------
// fp32 -> (hi, lo) bf16 split
// ---------------------------------------------------------------------------
__global__ void split_fp32(const float* __restrict__ x, __nv_bfloat16* __restrict__ hi,
                           __nv_bfloat16* __restrict__ lo, int n4)
{
    int i = blockIdx.x * blockDim.x + threadIdx.x;
    if (i >= n4) return;
    float4 v = ((const float4*)x)[i];
    float f[4] = {v.x, v.y, v.z, v.w};
    uint32_t hb[4], lb[4];
#pragma unroll
    for (int j = 0; j < 4; ++j) {
        __nv_bfloat16 h = __float2bfloat16(f[j]);
        float r = f[j] - __bfloat162float(h);
        __nv_bfloat16 l = __float2bfloat16(r);
        hb[j] = (uint32_t)__bfloat16_as_ushort(h);
        lb[j] = (uint32_t)__bfloat16_as_ushort(l);
    }
    ((uint2*)hi)[i] = make_uint2(hb[0] | (hb[1] << 16), hb[2] | (hb[3] << 16));
    ((uint2*)lo)[i] = make_uint2(lb[0] | (lb[1] << 16), lb[2] | (lb[3] << 16));
}

// ---------------------------------------------------------------------------
// Fused mma.sync 3-split GEMM: C = A[M,K]*B[N,K]^T (fp32-equivalent).
// Per 64-K chunk: stage AH,AL,BH,BL once, run 3 mma passes (hh, lh, hl).
// 128x128 CTA, 8 warps (2m x 4n), warp tile 64x32. 3-stage cp.async pipeline,
// XOR-swizzled 128B-pitch smem, 1 barrier/chunk.
// ---------------------------------------------------------------------------
__global__ __launch_bounds__(256, 1)
void gemm3x(const __nv_bfloat16* __restrict__ Ahi, const __nv_bfloat16* __restrict__ Alo,
            const __nv_bfloat16* __restrict__ Bhi, const __nv_bfloat16* __restrict__ Blo,
            float* __restrict__ Cf, __nv_bfloat16* __restrict__ Chi,
            __nv_bfloat16* __restrict__ Clo, int N)
{
    extern __shared__ __align__(16) char smraw[];
    const uint32_t sbase = smem_u32(smraw);

    const int tid  = threadIdx.x;
    const int wid  = tid >> 5;
    const int lane = tid & 31;
    const int m0   = blockIdx.y * 128;
    const int n0   = blockIdx.x * 128;

    // loader mapping: 4096 cp16 slots per stage, 16 per thread
    // slot s: tile tn = s>>10 (0 AH,1 AL,2 BH,3 BL), row=(s>>3)&127, unit u=s&7
    const __nv_bfloat16* gbase[4] = {Ahi, Alo, Bhi, Blo};

    // warp compute mapping (2m x 4n), warp tile 64x32
    const int wm = wid & 1;
    const int wn = wid >> 1;
    uint32_t arow[4], aswr[4];
#pragma unroll
    for (int i = 0; i < 4; ++i) {
        const int r = wm * 64 + i * 16 + (lane & 15);
        arow[i] = (uint32_t)(r * 128);
        aswr[i] = (uint32_t)((r & 7) << 4);
    }
    uint32_t brow[2], bswr[2];
#pragma unroll
    for (int jp = 0; jp < 2; ++jp) {
        const int r = wn * 32 + jp * 16 + (lane & 15);
        brow[jp] = (uint32_t)(r * 128);
        bswr[jp] = (uint32_t)((r & 7) << 4);
    }
    const uint32_t ubase = (uint32_t)((lane >> 4) * 16);

    float acc[4][4][4];
#pragma unroll
    for (int i = 0; i < 4; ++i)
#pragma unroll
        for (int j = 0; j < 4; ++j)
#pragma unroll
            for (int v = 0; v < 4; ++v) acc[i][j][v] = 0.f;

    auto issue = [&](int c, int stage) {
        const int k0 = c * 64;
        const uint32_t so = sbase + (uint32_t)(stage * GSTGB);
#pragma unroll
        for (int q = 0; q < 16; ++q) {
            const int s   = tid + (q << 8);
            const int tn  = s >> 10;
            const int row = (s >> 3) & 127;
            const int u   = s & 7;
            const int gr  = ((tn < 2) ? m0 : n0) + row;
            const uint32_t sw = (uint32_t)(((u * 16) ^ ((row & 7) << 4)) + row * 128);
            cp16(so + (uint32_t)tn * GTILB + sw,
                 gbase[tn] + (size_t)gr * EE + k0 + u * 8);
        }
        cp_commit();
    };

    issue(0, 0);
    issue(1, 1);

    int stage = 0;
    for (int c = 0; c < 16; ++c) {
        if (c + 1 < 16) cp_wait1(); else cp_wait0();
        __syncthreads();
        if (c + 2 < 16) issue(c + 2, (stage + 2) % 3);

        const uint32_t sb = sbase + (uint32_t)(stage * GSTGB);
#pragma unroll
        for (int ks = 0; ks < 4; ++ks) {
            const uint32_t cb = ubase + (uint32_t)(ks * 32);
            uint32_t aH[4][4], aL[4][4], bH[2][4], bL[2][4];
#pragma unroll
            for (int i = 0; i < 4; ++i) {
                const uint32_t ao = arow[i] + (cb ^ aswr[i]);
                ldm4(sb + ao, aH[i]);
                ldm4(sb + GTILB + ao, aL[i]);
            }
#pragma unroll
            for (int jp = 0; jp < 2; ++jp) {
                const uint32_t bo = brow[jp] + (cb ^ bswr[jp]);
                ldm4(sb + 2 * GTILB + bo, bH[jp]);
                ldm4(sb + 3 * GTILB + bo, bL[jp]);
            }
#pragma unroll
            for (int i = 0; i < 4; ++i)
#pragma unroll
                for (int j = 0; j < 4; ++j) {
                    const int jp = j >> 1, od = j & 1;
                    mma_bf16(acc[i][j], aH[i], bH[jp][od], bH[jp][od + 2]);
                    mma_bf16(acc[i][j], aL[i], bH[jp][od], bH[jp][od + 2]);
                    mma_bf16(acc[i][j], aH[i], bL[jp][od], bL[jp][od + 2]);
                }
        }
        stage = (stage + 1) % 3;
    }

    const int gr  = lane >> 2;
    const int gc2 = (lane & 3) * 2;
#pragma unroll
    for (int i = 0; i < 4; ++i) {
        const int row = m0 + wm * 64 + i * 16 + gr;
#pragma unroll
        for (int j = 0; j < 4; ++j) {
            const int col = n0 + wn * 32 + j * 8 + gc2;
            if (Cf) {
                *(float2*)(Cf + (size_t)row * N + col) =
                    make_float2(acc[i][j][0], acc[i][j][1]);
                *(float2*)(Cf + (size_t)(row + 8) * N + col) =
                    make_float2(acc[i][j][2], acc[i][j][3]);
            } else {
#pragma unroll
                for (int rr = 0; rr < 2; ++rr) {
                    float v0 = acc[i][j][rr * 2], v1 = acc[i][j][rr * 2 + 1];
                    __nv_bfloat16 h0 = __float2bfloat16(v0);
                    __nv_bfloat16 h1 = __float2bfloat16(v1);
                    __nv_bfloat16 l0 = __float2bfloat16(v0 - __bfloat162float(h0));
                    __nv_bfloat16 l1 = __float2bfloat16(v1 - __bfloat162float(h1));
                    const size_t off = (size_t)(row + rr * 8) * N + col;
                    *(uint32_t*)(Chi + off) = pack2bf(h0, h1);
                    *(uint32_t*)(Clo + off) = pack2bf(l0, l1);
                }
            }
        }
    }
}

// ---------------------------------------------------------------------------
// Tensor-core flash attention, causal, bf16 3-split (unchanged; validated).
// ---------------------------------------------------------------------------
__global__ __launch_bounds__(256, 2)
void attn_tc(const __nv_bfloat16* __restrict__ qkvh,
             const __nv_bfloat16* __restrict__ qkvl,
             __nv_bfloat16* __restrict__ ahi, __nv_bfloat16* __restrict__ alo)
{
    extern __shared__ __align__(16) char smA[];
    const uint32_t sQ  = smem_u32(smA);
    const uint32_t sKV = sQ + AQBYTES;

    const int tid  = threadIdx.x;
    const int wid  = tid >> 5;
    const int lane = tid & 31;
    const int qb   = (int)gridDim.x - 1 - (int)blockIdx.x;
    const int h    = blockIdx.y;
    const int b    = blockIdx.z;

    const size_t rowQ0 = (size_t)(b * LL + qb * QB);
    const size_t rowB  = (size_t)(b * LL);

#pragma unroll
    for (int i = 0; i < 8; ++i) {
        int s = tid + (i << 8);
        int half = s >> 10;
        int row  = (s >> 3) & 127;
        int u    = s & 7;
        const __nv_bfloat16* src = (half ? qkvl : qkvh)
            + (rowQ0 + row) * (3 * EE) + h * DD + u * 8;
        cp16(sQ + half * 18432 + row * APITCH + u * 16, src);
    }
    auto issue_kv = [&](int kb, uint32_t dst) {
#pragma unroll
        for (int i = 0; i < 8; ++i) {
            int s = tid + (i << 8);
            int tn  = s >> 9;
            int row = (s >> 3) & 63;
            int u   = s & 7;
            const __nv_bfloat16* base = (tn & 1) ? qkvl : qkvh;
            int col = ((tn >> 1) ? 2 * EE : EE) + h * DD + u * 8;
            cp16(dst + tn * AKTILE + row * APITCH + u * 16,
                 base + (rowB + (size_t)kb * KVB + row) * (3 * EE) + col);
        }
    };
    issue_kv(0, sKV);
    cp_commit();
    cp_wait0();
    __syncthreads();

    const int q0   = wid * 16;
    const int qmin = qb * QB + q0;
    const int rA = lane & 15, uA = (lane >> 4);
    const int rT = (lane & 7) + ((lane >> 4) << 3);
    const int uT = (lane >> 3) & 1;

    float m0 = -1e30f, m1 = -1e30f, l0 = 0.f, l1 = 0.f;
    float O[8][4];
#pragma unroll
    for (int j = 0; j < 8; ++j)
#pragma unroll
        for (int v = 0; v < 4; ++v) O[j][v] = 0.f;

    const int nkb = 2 * qb + 2;
    int buf = 0;
    for (int kb = 0; kb < nkb; ++kb) {
        if (kb + 1 < nkb) { issue_kv(kb + 1, sKV + (buf ^ 1) * ASTAGE); cp_commit(); }
        const uint32_t st = sKV + buf * ASTAGE;
        const bool skip = (kb * KVB > qmin + 15);
        if (!skip) {
            float acc[8][4];
#pragma unroll
            for (int j = 0; j < 8; ++j)
#pragma unroll
                for (int v = 0; v < 4; ++v) acc[j][v] = 0.f;

#pragma unroll
            for (int ks = 0; ks < 4; ++ks) {
                uint32_t aH[4], aL[4];
                ldm4(sQ + (q0 + rA) * APITCH + uA * 16 + ks * 32, aH);
                ldm4(sQ + 18432 + (q0 + rA) * APITCH + uA * 16 + ks * 32, aL);
#pragma unroll
                for (int jp = 0; jp < 4; ++jp) {
                    uint32_t bH[4], bL[4];
                    const uint32_t ko = (uint32_t)((jp * 16 + rA) * APITCH + uA * 16 + ks * 32);
                    ldm4(st + ko, bH);
                    mma_bf16(acc[2 * jp],     aH, bH[0], bH[2]);
                    mma_bf16(acc[2 * jp + 1], aH, bH[1], bH[3]);
                    mma_bf16(acc[2 * jp],     aL, bH[0], bH[2]);
                    mma_bf16(acc[2 * jp + 1], aL, bH[1], bH[3]);
                    ldm4(st + AKTILE + ko, bL);
                    mma_bf16(acc[2 * jp],     aH, bL[0], bL[2]);
                    mma_bf16(acc[2 * jp + 1], aH, bL[1], bL[3]);
                }
            }

            const int r0 = qmin + (lane >> 2), r1 = r0 + 8;
            const bool needmask = (kb * KVB + KVB - 1 > qmin);
#pragma unroll
            for (int j = 0; j < 8; ++j) {
                acc[j][0] *= 0.125f; acc[j][1] *= 0.125f;
                acc[j][2] *= 0.125f; acc[j][3] *= 0.125f;
                if (needmask) {
                    const int key = kb * KVB + j * 8 + ((lane & 3) << 1);
                    if (key     > r0) acc[j][0] = -1e30f;
                    if (key + 1 > r0) acc[j][1] = -1e30f;
                    if (key     > r1) acc[j][2] = -1e30f;
                    if (key + 1 > r1) acc[j][3] = -1e30f;
                }
            }

            float mx0 = -1e30f, mx1 = -1e30f;
#pragma unroll
            for (int j = 0; j < 8; ++j) {
                mx0 = fmaxf(mx0, fmaxf(acc[j][0], acc[j][1]));
                mx1 = fmaxf(mx1, fmaxf(acc[j][2], acc[j][3]));
            }
            mx0 = fmaxf(mx0, __shfl_xor_sync(0xffffffffu, mx0, 1));
            mx0 = fmaxf(mx0, __shfl_xor_sync(0xffffffffu, mx0, 2));
            mx1 = fmaxf(mx1, __shfl_xor_sync(0xffffffffu, mx1, 1));
            mx1 = fmaxf(mx1, __shfl_xor_sync(0xffffffffu, mx1, 2));
            const float mn0 = fmaxf(m0, mx0), mn1 = fmaxf(m1, mx1);
            const float c0 = __expf(m0 - mn0), c1 = __expf(m1 - mn1);
            float s0 = 0.f, s1 = 0.f;
#pragma unroll
            for (int j = 0; j < 8; ++j) {
                acc[j][0] = __expf(acc[j][0] - mn0); s0 += acc[j][0];
                acc[j][1] = __expf(acc[j][1] - mn0); s0 += acc[j][1];
                acc[j][2] = __expf(acc[j][2] - mn1); s1 += acc[j][2];
                acc[j][3] = __expf(acc[j][3] - mn1); s1 += acc[j][3];
            }
            s0 += __shfl_xor_sync(0xffffffffu, s0, 1);
            s0 += __shfl_xor_sync(0xffffffffu, s0, 2);
            s1 += __shfl_xor_sync(0xffffffffu, s1, 1);
            s1 += __shfl_xor_sync(0xffffffffu, s1, 2);
            l0 = l0 * c0 + s0; l1 = l1 * c1 + s1;
            m0 = mn0; m1 = mn1;
#pragma unroll
            for (int j = 0; j < 8; ++j) {
                O[j][0] *= c0; O[j][1] *= c0;
                O[j][2] *= c1; O[j][3] *= c1;
            }

#pragma unroll
            for (int t = 0; t < 4; ++t) {
                uint32_t aPh[4], aPl[4];
#pragma unroll
                for (int hf = 0; hf < 2; ++hf) {
                    const float* pv = acc[2 * t + hf];
                    __nv_bfloat16 h0 = __float2bfloat16(pv[0]);
                    __nv_bfloat16 h1 = __float2bfloat16(pv[1]);
                    __nv_bfloat16 h2 = __float2bfloat16(pv[2]);
                    __nv_bfloat16 h3 = __float2bfloat16(pv[3]);
                    aPh[hf * 2]     = pack2bf(h0, h1);
                    aPh[hf * 2 + 1] = pack2bf(h2, h3);
                    aPl[hf * 2]     = pack2bf(
                        __float2bfloat16(pv[0] - __bfloat162float(h0)),
                        __float2bfloat16(pv[1] - __bfloat162float(h1)));
                    aPl[hf * 2 + 1] = pack2bf(
                        __float2bfloat16(pv[2] - __bfloat162float(h2)),
                        __float2bfloat16(pv[3] - __bfloat162float(h3)));
                }
#pragma unroll
                for (int jp = 0; jp < 4; ++jp) {
                    uint32_t vH[4], vL[4];
                    const uint32_t vo = (uint32_t)((t * 16 + rT) * APITCH
                                                   + (jp * 2 + uT) * 16);
                    ldm4t(st + 2 * AKTILE + vo, vH);
                    mma_bf16(O[2 * jp],     aPh, vH[0], vH[2]);
                    mma_bf16(O[2 * jp + 1], aPh, vH[1], vH[3]);
                    mma_bf16(O[2 * jp],     aPl, vH[0], vH[2]);
                    mma_bf16(O[2 * jp + 1], aPl, vH[1], vH[3]);
                    ldm4t(st + 3 * AKTILE + vo, vL);
                    mma_bf16(O[2 * jp],     aPh, vL[0], vL[2]);
                    mma_bf16(O[2 * jp + 1], aPh, vL[1], vL[3]);
                }
            }
        }
        if (kb + 1 < nkb) cp_wait0();
        __syncthreads();
        buf ^= 1;
    }

    const float i0 = 1.f / l0, i1 = 1.f / l1;
    const size_t g0 = (rowQ0 + q0 + (lane >> 2)) * EE + h * DD;
    const size_t g1 = g0 + (size_t)8 * EE;
#pragma unroll
    for (int j = 0; j < 8; ++j) {
        const int col = j * 8 + ((lane & 3) << 1);
#pragma unroll
        for (int rr = 0; rr < 2; ++rr) {
            const float v0 = O[j][rr * 2] * (rr ? i1 : i0);
            const float v1 = O[j][rr * 2 + 1] * (rr ? i1 : i0);
            __nv_bfloat16 h0 = __float2bfloat16(v0);
            __nv_bfloat16 h1 = __float2bfloat16(v1);
            __nv_bfloat16 lo0 = __float2bfloat16(v0 - __bfloat162float(h0));
            __nv_bfloat16 lo1 = __float2bfloat16(v1 - __bfloat162float(h1));
            const size_t off = (rr ? g1 : g0) + col;
            *(uint32_t*)(ahi + off) = pack2bf(h0, h1);
            *(uint32_t*)(alo + off) = pack2bf(lo0, lo1);
        }
    }
}

// ---------------------------------------------------------------------------
extern "C" void kernel_launch(void* const* d_in, const int* in_sizes, int n_in,
                              void* d_out, int out_size)
{
    (void)in_sizes; (void)n_in; (void)out_size;
    const float* net_in = (const float*)d_in[0];
    const float* W_qkv  = (const float*)d_in[1];
    const float* W_out  = (const float*)d_in[2];
    float* outp = (float*)d_out;

    __nv_bfloat16 *xhi, *xlo, *wqhi, *wqlo, *wohi, *wolo, *qh, *ql, *ahi, *alo;
    cudaGetSymbolAddress((void**)&xhi,  g_xhi);
    cudaGetSymbolAddress((void**)&xlo,  g_xlo);
    cudaGetSymbolAddress((void**)&wqhi, g_wqhi);
    cudaGetSymbolAddress((void**)&wqlo, g_wqlo);
    cudaGetSymbolAddress((void**)&wohi, g_wohi);
    cudaGetSymbolAddress((void**)&wolo, g_wolo);
    cudaGetSymbolAddress((void**)&qh,   g_qkvhi);
    cudaGetSymbolAddress((void**)&ql,   g_qkvlo);
    cudaGetSymbolAddress((void**)&ahi,  g_ahi);
    cudaGetSymbolAddress((void**)&alo,  g_alo);

    cudaFuncSetAttribute(gemm3x,
                         cudaFuncAttributeMaxDynamicSharedMemorySize, GSMEM);
    cudaFuncSetAttribute(attn_tc,
                         cudaFuncAttributeMaxDynamicSharedMemorySize, ASMEM);

    // 0) input/weight splits
    {
        int n4 = (MM * EE) / 4;
        split_fp32<<<(n4 + 255) / 256, 256>>>(net_in, xhi, xlo, n4);
        n4 = (3 * EE * EE) / 4;
        split_fp32<<<(n4 + 255) / 256, 256>>>(W_qkv, wqhi, wqlo, n4);
        n4 = (EE * EE) / 4;
        split_fp32<<<(n4 + 255) / 256, 256>>>(W_out, wohi, wolo, n4);
    }

    // 1) QKV projection -> split-bf16 qkv
    dim3 g1((3 * EE) / 128, MM / 128);
    gemm3x<<<g1, 256, GSMEM>>>(xhi, xlo, wqhi, wqlo, nullptr, qh, ql, 3 * EE);

    // 2) Tensor-core causal flash attention -> split-bf16 activations
    dim3 ga(LL / QB, HH, BB);
    attn_tc<<<ga, 256, ASMEM>>>(qh, ql, ahi, alo);

    // 3) Output projection -> fp32 d_out
    dim3 g3(EE / 128, MM / 128);
    gemm3x<<<g3, 256, GSMEM>>>(ahi, alo, wohi, wolo, outp, nullptr, nullptr, EE);
}

// round 14
// speedup vs baseline: 1.0103x; 1.0103x over previous
#include <cuda_runtime.h>
#include <cuda_bf16.h>
#include <cstdint>

// Problem constants
#define BB   2
#define LL   2048
#define HH   16
#define DD   64
#define EE   1024
#define MM   (BB * LL)      /* 4096 rows */
#define QB   128
#define KVB  64

// Tensor-GEMM smem geometry (R11, validated): K-chunk 64 bf16, 144B pitch
#define GROWB   144
#define GTILEB  (128 * GROWB)          /* 18432 B per operand tile */
#define GBUFB   (2 * GTILEB)           /* A+B one stage = 36864 */
#define GSMEM   (3 * GBUFB)            /* 3-stage = 110592 B */
// Hybrid adds fp32 sub-kernel smem after the tensor region
#define FSMEM_A 8192                   /* Asf[2][8][128] f32 */
#define FSMEM_B 4096                   /* Bsf[2][8][64]  f32 */
#define HSMEM   (GSMEM + FSMEM_A + FSMEM_B)   /* 122880 */

// Attention smem geometry (unchanged, validated)
#define APITCH  144
#define AKTILE  (64 * APITCH)
#define ASTAGE  (4 * AKTILE)
#define AQBYTES (2 * 128 * APITCH)
#define ASMEM   (AQBYTES + 2 * ASTAGE)

// Named barriers: tensor group (warps 0-7), fp32 group (warps 8-11)
#define BART() asm volatile("bar.sync 1, 256;" ::: "memory")
#define BARF() asm volatile("bar.sync 2, 128;" ::: "memory")

// ---------------------------------------------------------------------------
// Scratch (device globals — no runtime allocation allowed)
// ---------------------------------------------------------------------------
__device__ __nv_bfloat16 g_xhi[(size_t)MM * EE];
__device__ __nv_bfloat16 g_xlo[(size_t)MM * EE];
__device__ __nv_bfloat16 g_wqhi[(size_t)3 * EE * EE];
__device__ __nv_bfloat16 g_wqlo[(size_t)3 * EE * EE];
__device__ __nv_bfloat16 g_wohi[(size_t)EE * EE];
__device__ __nv_bfloat16 g_wolo[(size_t)EE * EE];
__device__ __nv_bfloat16 g_qkvhi[(size_t)MM * 3 * EE];
__device__ __nv_bfloat16 g_qkvlo[(size_t)MM * 3 * EE];
__device__ __nv_bfloat16 g_ahi[(size_t)MM * EE];
__device__ __nv_bfloat16 g_alo[(size_t)MM * EE];

// ---------------------------------------------------------------------------
// PTX helpers (baseline ISA only)
// ---------------------------------------------------------------------------
__device__ __forceinline__ uint32_t smem_u32(const void* p) {
    uint32_t a;
    asm("{ .reg .u64 t; cvta.to.shared.u64 t, %1; cvt.u32.u64 %0, t; }"
        : "=r"(a) : "l"(p));
    return a;
}
__device__ __forceinline__ void cp16(uint32_t saddr, const void* gaddr) {
    asm volatile("cp.async.cg.shared.global [%0], [%1], 16;"
                 :: "r"(saddr), "l"(gaddr) : "memory");
}
__device__ __forceinline__ void cp_commit() {
    asm volatile("cp.async.commit_group;" ::: "memory");
}
__device__ __forceinline__ void cp_wait1() {
    asm volatile("cp.async.wait_group 1;" ::: "memory");
}
__device__ __forceinline__ void cp_wait0() {
    asm volatile("cp.async.wait_group 0;" ::: "memory");
}
__device__ __forceinline__ void ldm4(uint32_t addr, uint32_t* r) {
    asm volatile("ldmatrix.sync.aligned.m8n8.x4.shared.b16 {%0,%1,%2,%3}, [%4];"
                 : "=r"(r[0]), "=r"(r[1]), "=r"(r[2]), "=r"(r[3]) : "r"(addr));
}
__device__ __forceinline__ void ldm4t(uint32_t addr, uint32_t* r) {
    asm volatile("ldmatrix.sync.aligned.m8n8.x4.trans.shared.b16 {%0,%1,%2,%3}, [%4];"
                 : "=r"(r[0]), "=r"(r[1]), "=r"(r[2]), "=r"(r[3]) : "r"(addr));
}
__device__ __forceinline__ void mma_bf16(float* c, const uint32_t* a,
                                         uint32_t b0, uint32_t b1) {
    asm volatile(
        "mma.sync.aligned.m16n8k16.row.col.f32.bf16.bf16.f32 "
        "{%0,%1,%2,%3}, {%4,%5,%6,%7}, {%8,%9}, {%0,%1,%2,%3};"
        : "+f"(c[0]), "+f"(c[1]), "+f"(c[2]), "+f"(c[3])
        : "r"(a[0]), "r"(a[1]), "r"(a[2]), "r"(a[3]), "r"(b0), "r"(b1));
}
__device__ __forceinline__ uint32_t pack2bf(__nv_bfloat16 x, __nv_bfloat16 y) {
    return (uint32_t)__bfloat16_as_ushort(x) |
           ((uint32_t)__bfloat16_as_ushort(y) << 16);
}

// ---------------------------------------------------------------------------
// fp32 -> (hi, lo) bf16 split
// ---------------------------------------------------------------------------
__global__ void split_fp32(const float* __restrict__ x, __nv_bfloat16* __restrict__ hi,
                           __nv_bfloat16* __restrict__ lo, int n4)
{
    int i = blockIdx.x * blockDim.x + threadIdx.x;
    if (i >= n4) return;
    float4 v = ((const float4*)x)[i];
    float f[4] = {v.x, v.y, v.z, v.w};
    uint32_t hb[4], lb[4];
#pragma unroll
    for (int j = 0; j < 4; ++j) {
        __nv_bfloat16 h = __float2bfloat16(f[j]);
        float r = f[j] - __bfloat162float(h);
        __nv_bfloat16 l = __float2bfloat16(r);
        hb[j] = (uint32_t)__bfloat16_as_ushort(h);
        lb[j] = (uint32_t)__bfloat16_as_ushort(l);
    }
    ((uint2*)hi)[i] = make_uint2(hb[0] | (hb[1] << 16), hb[2] | (hb[3] << 16));
    ((uint2*)lo)[i] = make_uint2(lb[0] | (lb[1] << 16), lb[2] | (lb[3] << 16));
}

// ---------------------------------------------------------------------------
// R11 mma.sync 3-split GEMM (validated): used for the output projection.
// ---------------------------------------------------------------------------
__global__ __launch_bounds__(256, 2)
void gemm3x(const __nv_bfloat16* __restrict__ Ahi, const __nv_bfloat16* __restrict__ Alo,
            const __nv_bfloat16* __restrict__ Bhi, const __nv_bfloat16* __restrict__ Blo,
            float* __restrict__ Cf, int N)
{
    extern __shared__ __align__(16) char smraw[];
    const uint32_t sbase = smem_u32(smraw);

    const int tid  = threadIdx.x;
    const int wid  = tid >> 5;
    const int lane = tid & 31;
    const int m0   = blockIdx.y * 128;
    const int n0   = blockIdx.x * 128;

    const int lr = tid >> 1;
    const int lh = tid & 1;
    const uint32_t sArow = (uint32_t)(lr * GROWB + lh * 64);
    const uint32_t sBrow = sArow + GTILEB;
    const size_t gAoff = (size_t)(m0 + lr) * EE + lh * 32;
    const size_t gBoff = (size_t)(n0 + lr) * EE + lh * 32;

    const int wm = wid & 1;
    const int wn = wid >> 1;
    uint32_t aoff[4], boff[2];
#pragma unroll
    for (int i = 0; i < 4; ++i)
        aoff[i] = (uint32_t)((wm * 64 + i * 16 + (lane & 15)) * GROWB + (lane >> 4) * 16);
#pragma unroll
    for (int jp = 0; jp < 2; ++jp)
        boff[jp] = (uint32_t)(GTILEB + (wn * 32 + jp * 16 + (lane & 15)) * GROWB
                              + (lane >> 4) * 16);

    float acc[4][4][4];
#pragma unroll
    for (int i = 0; i < 4; ++i)
#pragma unroll
        for (int j = 0; j < 4; ++j)
#pragma unroll
            for (int v = 0; v < 4; ++v) acc[i][j][v] = 0.f;

    auto issue = [&](int c, int stage) {
        const int ph = c >> 4;
        const int k0 = (c & 15) * 64;
        const __nv_bfloat16* ga = ((ph == 1) ? Alo : Ahi) + gAoff + k0;
        const __nv_bfloat16* gb = ((ph == 2) ? Blo : Bhi) + gBoff + k0;
        const uint32_t so = sbase + (uint32_t)(stage * GBUFB);
#pragma unroll
        for (int q = 0; q < 4; ++q) {
            cp16(so + sArow + q * 16, ga + q * 8);
            cp16(so + sBrow + q * 16, gb + q * 8);
        }
        cp_commit();
    };

    issue(0, 0);
    issue(1, 1);

    int stage = 0;
    for (int c = 0; c < 48; ++c) {
        if (c + 1 < 48) cp_wait1(); else cp_wait0();
        __syncthreads();
        if (c + 2 < 48) issue(c + 2, (stage + 2) % 3);

        const uint32_t sb = sbase + (uint32_t)(stage * GBUFB);
#pragma unroll
        for (int ks = 0; ks < 4; ++ks) {
            uint32_t af[4][4], bfr[2][4];
#pragma unroll
            for (int i = 0; i < 4; ++i) ldm4(sb + aoff[i] + ks * 32, af[i]);
#pragma unroll
            for (int jp = 0; jp < 2; ++jp) ldm4(sb + boff[jp] + ks * 32, bfr[jp]);
#pragma unroll
            for (int i = 0; i < 4; ++i)
#pragma unroll
                for (int j = 0; j < 4; ++j) {
                    const int jp = j >> 1, od = j & 1;
                    mma_bf16(acc[i][j], af[i], bfr[jp][od], bfr[jp][od + 2]);
                }
        }
        stage = (stage + 1) % 3;
    }

    const int gr  = lane >> 2;
    const int gc2 = (lane & 3) * 2;
#pragma unroll
    for (int i = 0; i < 4; ++i) {
        const int row = m0 + wm * 64 + i * 16 + gr;
#pragma unroll
        for (int j = 0; j < 4; ++j) {
            const int col = n0 + wn * 32 + j * 8 + gc2;
            *(float2*)(Cf + (size_t)row * N + col) =
                make_float2(acc[i][j][0], acc[i][j][1]);
            *(float2*)(Cf + (size_t)(row + 8) * N + col) =
                make_float2(acc[i][j][2], acc[i][j][3]);
        }
    }
}

// ---------------------------------------------------------------------------
// Hybrid GEMM for QKV: 384 threads, tile 128 x 192.
//  warps 0-7 : R11 tensor 3-split path, cols [n0, n0+128), bar.sync 1
//  warps 8-11: fp32 FFMA sgemm (R4 structure), cols [n0+128, n0+192), bar.sync 2
// Both write split-bf16 outputs. Fully independent pipelines per CTA.
// ---------------------------------------------------------------------------
__global__ __launch_bounds__(384, 1)
void gemm_hyb(const __nv_bfloat16* __restrict__ Ahi, const __nv_bfloat16* __restrict__ Alo,
              const __nv_bfloat16* __restrict__ Bhi, const __nv_bfloat16* __restrict__ Blo,
              const float* __restrict__ Af, const float* __restrict__ Bf,
              __nv_bfloat16* __restrict__ Chi, __nv_bfloat16* __restrict__ Clo, int N)
{
    extern __shared__ __align__(16) char smraw[];
    const int tid = threadIdx.x;
    const int m0  = blockIdx.y * 128;
    const int n0  = blockIdx.x * 192;

    if (tid < 256) {
        // ================= tensor sub-kernel (R11 body, bar 1) =============
        const uint32_t sbase = smem_u32(smraw);
        const int wid  = tid >> 5;
        const int lane = tid & 31;

        const int lr = tid >> 1;
        const int lh = tid & 1;
        const uint32_t sArow = (uint32_t)(lr * GROWB + lh * 64);
        const uint32_t sBrow = sArow + GTILEB;
        const size_t gAoff = (size_t)(m0 + lr) * EE + lh * 32;
        const size_t gBoff = (size_t)(n0 + lr) * EE + lh * 32;

        const int wm = wid & 1;
        const int wn = wid >> 1;
        uint32_t aoff[4], boff[2];
#pragma unroll
        for (int i = 0; i < 4; ++i)
            aoff[i] = (uint32_t)((wm * 64 + i * 16 + (lane & 15)) * GROWB + (lane >> 4) * 16);
#pragma unroll
        for (int jp = 0; jp < 2; ++jp)
            boff[jp] = (uint32_t)(GTILEB + (wn * 32 + jp * 16 + (lane & 15)) * GROWB
                                  + (lane >> 4) * 16);

        float acc[4][4][4];
#pragma unroll
        for (int i = 0; i < 4; ++i)
#pragma unroll
            for (int j = 0; j < 4; ++j)
#pragma unroll
                for (int v = 0; v < 4; ++v) acc[i][j][v] = 0.f;

        auto issue = [&](int c, int stage) {
            const int ph = c >> 4;
            const int k0 = (c & 15) * 64;
            const __nv_bfloat16* ga = ((ph == 1) ? Alo : Ahi) + gAoff + k0;
            const __nv_bfloat16* gb = ((ph == 2) ? Blo : Bhi) + gBoff + k0;
            const uint32_t so = sbase + (uint32_t)(stage * GBUFB);
#pragma unroll
            for (int q = 0; q < 4; ++q) {
                cp16(so + sArow + q * 16, ga + q * 8);
                cp16(so + sBrow + q * 16, gb + q * 8);
            }
            cp_commit();
        };

        issue(0, 0);
        issue(1, 1);

        int stage = 0;
        for (int c = 0; c < 48; ++c) {
            if (c + 1 < 48) cp_wait1(); else cp_wait0();
            BART();
            if (c + 2 < 48) issue(c + 2, (stage + 2) % 3);

            const uint32_t sb = sbase + (uint32_t)(stage * GBUFB);
#pragma unroll
            for (int ks = 0; ks < 4; ++ks) {
                uint32_t af[4][4], bfr[2][4];
#pragma unroll
                for (int i = 0; i < 4; ++i) ldm4(sb + aoff[i] + ks * 32, af[i]);
#pragma unroll
                for (int jp = 0; jp < 2; ++jp) ldm4(sb + boff[jp] + ks * 32, bfr[jp]);
#pragma unroll
                for (int i = 0; i < 4; ++i)
#pragma unroll
                    for (int j = 0; j < 4; ++j) {
                        const int jp = j >> 1, od = j & 1;
                        mma_bf16(acc[i][j], af[i], bfr[jp][od], bfr[jp][od + 2]);
                    }
            }
            stage = (stage + 1) % 3;
        }

        const int gr  = lane >> 2;
        const int gc2 = (lane & 3) * 2;
#pragma unroll
        for (int i = 0; i < 4; ++i) {
            const int row = m0 + wm * 64 + i * 16 + gr;
#pragma unroll
            for (int j = 0; j < 4; ++j) {
                const int col = n0 + wn * 32 + j * 8 + gc2;
#pragma unroll
                for (int rr = 0; rr < 2; ++rr) {
                    float v0 = acc[i][j][rr * 2], v1 = acc[i][j][rr * 2 + 1];
                    __nv_bfloat16 h0 = __float2bfloat16(v0);
                    __nv_bfloat16 h1 = __float2bfloat16(v1);
                    __nv_bfloat16 l0 = __float2bfloat16(v0 - __bfloat162float(h0));
                    __nv_bfloat16 l1 = __float2bfloat16(v1 - __bfloat162float(h1));
                    const size_t off = (size_t)(row + rr * 8) * N + col;
                    *(uint32_t*)(Chi + off) = pack2bf(h0, h1);
                    *(uint32_t*)(Clo + off) = pack2bf(l0, l1);
                }
            }
        }
    } else {
        // ================= fp32 sub-kernel (R4 structure, bar 2) ===========
        const int t2  = tid - 256;            // 0..127
        const int ty2 = t2 >> 3;              // 0..15  (m octet)
        const int tx2 = t2 & 7;               // 0..7   (n octet)
        const int n0f = n0 + 128;
        float* Asf = (float*)(smraw + GSMEM);             // [2][8][128]
        float* Bsf = (float*)(smraw + GSMEM + FSMEM_A);   // [2][8][64]

        const float* Ap = Af + (size_t)(m0 + t2) * EE;
        const float* Bp = Bf + (size_t)(n0f + (t2 >> 1)) * EE + (t2 & 1) * 4;
        const int bk0 = (t2 & 1) * 4;         // B k-offset this thread fills
        const int brw = t2 >> 1;              // B row (0..63)

        float accf[8][8];
#pragma unroll
        for (int i = 0; i < 8; ++i)
#pragma unroll
            for (int j = 0; j < 8; ++j) accf[i][j] = 0.f;

        float4 av0 = *(const float4*)Ap;
        float4 av1 = *(const float4*)(Ap + 4);
        float4 bv  = *(const float4*)Bp;
        {
            float ax[8] = {av0.x, av0.y, av0.z, av0.w, av1.x, av1.y, av1.z, av1.w};
#pragma unroll
            for (int j = 0; j < 8; ++j) Asf[j * 128 + t2] = ax[j];
            float bx[4] = {bv.x, bv.y, bv.z, bv.w};
#pragma unroll
            for (int j = 0; j < 4; ++j) Bsf[(bk0 + j) * 64 + brw] = bx[j];
        }
        BARF();

        int buff = 0;
        for (int kb = 0; kb < 128; ++kb) {
            const bool more = (kb + 1 < 128);
            if (more) {
                const int k0 = (kb + 1) * 8;
                av0 = *(const float4*)(Ap + k0);
                av1 = *(const float4*)(Ap + k0 + 4);
                bv  = *(const float4*)(Bp + k0);
            }
#pragma unroll
            for (int k = 0; k < 8; ++k) {
                float a[8], b[8];
                *(float4*)&a[0] = *(const float4*)&Asf[(buff * 8 + k) * 128 + ty2 * 8];
                *(float4*)&a[4] = *(const float4*)&Asf[(buff * 8 + k) * 128 + ty2 * 8 + 4];
                *(float4*)&b[0] = *(const float4*)&Bsf[(buff * 8 + k) * 64 + tx2 * 8];
                *(float4*)&b[4] = *(const float4*)&Bsf[(buff * 8 + k) * 64 + tx2 * 8 + 4];
#pragma unroll
                for (int i = 0; i < 8; ++i)
#pragma unroll
                    for (int j = 0; j < 8; ++j)
                        accf[i][j] = fmaf(a[i], b[j], accf[i][j]);
            }
            if (more) {
                const int nb = buff ^ 1;
                float ax[8] = {av0.x, av0.y, av0.z, av0.w, av1.x, av1.y, av1.z, av1.w};
#pragma unroll
                for (int j = 0; j < 8; ++j) Asf[(nb * 8 + j) * 128 + t2] = ax[j];
                float bx[4] = {bv.x, bv.y, bv.z, bv.w};
#pragma unroll
                for (int j = 0; j < 4; ++j) Bsf[(nb * 8 + bk0 + j) * 64 + brw] = bx[j];
                BARF();
                buff = nb;
            }
        }

        // epilogue: split-bf16 store, rows m0+ty2*8+i, cols n0f+tx2*8+j
#pragma unroll
        for (int i = 0; i < 8; ++i) {
            const int row = m0 + ty2 * 8 + i;
#pragma unroll
            for (int j = 0; j < 8; j += 2) {
                const int col = n0f + tx2 * 8 + j;
                float v0 = accf[i][j], v1 = accf[i][j + 1];
                __nv_bfloat16 h0 = __float2bfloat16(v0);
                __nv_bfloat16 h1 = __float2bfloat16(v1);
                __nv_bfloat16 l0 = __float2bfloat16(v0 - __bfloat162float(h0));
                __nv_bfloat16 l1 = __float2bfloat16(v1 - __bfloat162float(h1));
                const size_t off = (size_t)row * N + col;
                *(uint32_t*)(Chi + off) = pack2bf(h0, h1);
                *(uint32_t*)(Clo + off) = pack2bf(l0, l1);
            }
        }
    }
}

// ---------------------------------------------------------------------------
// Tensor-core flash attention, causal, bf16 3-split (unchanged; validated).
// ---------------------------------------------------------------------------
__global__ __launch_bounds__(256, 2)
void attn_tc(const __nv_bfloat16* __restrict__ qkvh,
             const __nv_bfloat16* __restrict__ qkvl,
             __nv_bfloat16* __restrict__ ahi, __nv_bfloat16* __restrict__ alo)
{
    extern __shared__ __align__(16) char smA[];
    const uint32_t sQ  = smem_u32(smA);
    const uint32_t sKV = sQ + AQBYTES;

    const int tid  = threadIdx.x;
    const int wid  = tid >> 5;
    const int lane = tid & 31;
    const int qb   = (int)gridDim.x - 1 - (int)blockIdx.x;
    const int h    = blockIdx.y;
    const int b    = blockIdx.z;

    const size_t rowQ0 = (size_t)(b * LL + qb * QB);
    const size_t rowB  = (size_t)(b * LL);

#pragma unroll
    for (int i = 0; i < 8; ++i) {
        int s = tid + (i << 8);
        int half = s >> 10;
        int row  = (s >> 3) & 127;
        int u    = s & 7;
        const __nv_bfloat16* src = (half ? qkvl : qkvh)
            + (rowQ0 + row) * (3 * EE) + h * DD + u * 8;
        cp16(sQ + half * 18432 + row * APITCH + u * 16, src);
    }
    auto issue_kv = [&](int kb, uint32_t dst) {
#pragma unroll
        for (int i = 0; i < 8; ++i) {
            int s = tid + (i << 8);
            int tn  = s >> 9;
            int row = (s >> 3) & 63;
            int u   = s & 7;
            const __nv_bfloat16* base = (tn & 1) ? qkvl : qkvh;
            int col = ((tn >> 1) ? 2 * EE : EE) + h * DD + u * 8;
            cp16(dst + tn * AKTILE + row * APITCH + u * 16,
                 base + (rowB + (size_t)kb * KVB + row) * (3 * EE) + col);
        }
    };
    issue_kv(0, sKV);
    cp_commit();
    cp_wait0();
    __syncthreads();

    const int q0   = wid * 16;
    const int qmin = qb * QB + q0;
    const int rA = lane & 15, uA = (lane >> 4);
    const int rT = (lane & 7) + ((lane >> 4) << 3);
    const int uT = (lane >> 3) & 1;

    float m0 = -1e30f, m1 = -1e30f, l0 = 0.f, l1 = 0.f;
    float O[8][4];
#pragma unroll
    for (int j = 0; j < 8; ++j)
#pragma unroll
        for (int v = 0; v < 4; ++v) O[j][v] = 0.f;

    const int nkb = 2 * qb + 2;
    int buf = 0;
    for (int kb = 0; kb < nkb; ++kb) {
        if (kb + 1 < nkb) { issue_kv(kb + 1, sKV + (buf ^ 1) * ASTAGE); cp_commit(); }
        const uint32_t st = sKV + buf * ASTAGE;
        const bool skip = (kb * KVB > qmin + 15);
        if (!skip) {
            float acc[8][4];
#pragma unroll
            for (int j = 0; j < 8; ++j)
#pragma unroll
                for (int v = 0; v < 4; ++v) acc[j][v] = 0.f;

#pragma unroll
            for (int ks = 0; ks < 4; ++ks) {
                uint32_t aH[4], aL[4];
                ldm4(sQ + (q0 + rA) * APITCH + uA * 16 + ks * 32, aH);
                ldm4(sQ + 18432 + (q0 + rA) * APITCH + uA * 16 + ks * 32, aL);
#pragma unroll
                for (int jp = 0; jp < 4; ++jp) {
                    uint32_t bH[4], bL[4];
                    const uint32_t ko = (uint32_t)((jp * 16 + rA) * APITCH + uA * 16 + ks * 32);
                    ldm4(st + ko, bH);
                    mma_bf16(acc[2 * jp],     aH, bH[0], bH[2]);
                    mma_bf16(acc[2 * jp + 1], aH, bH[1], bH[3]);
                    mma_bf16(acc[2 * jp],     aL, bH[0], bH[2]);
                    mma_bf16(acc[2 * jp + 1], aL, bH[1], bH[3]);
                    ldm4(st + AKTILE + ko, bL);
                    mma_bf16(acc[2 * jp],     aH, bL[0], bL[2]);
                    mma_bf16(acc[2 * jp + 1], aH, bL[1], bL[3]);
                }
            }

            const int r0 = qmin + (lane >> 2), r1 = r0 + 8;
            const bool needmask = (kb * KVB + KVB - 1 > qmin);
#pragma unroll
            for (int j = 0; j < 8; ++j) {
                acc[j][0] *= 0.125f; acc[j][1] *= 0.125f;
                acc[j][2] *= 0.125f; acc[j][3] *= 0.125f;
                if (needmask) {
                    const int key = kb * KVB + j * 8 + ((lane & 3) << 1);
                    if (key     > r0) acc[j][0] = -1e30f;
                    if (key + 1 > r0) acc[j][1] = -1e30f;
                    if (key     > r1) acc[j][2] = -1e30f;
                    if (key + 1 > r1) acc[j][3] = -1e30f;
                }
            }

            float mx0 = -1e30f, mx1 = -1e30f;
#pragma unroll
            for (int j = 0; j < 8; ++j) {
                mx0 = fmaxf(mx0, fmaxf(acc[j][0], acc[j][1]));
                mx1 = fmaxf(mx1, fmaxf(acc[j][2], acc[j][3]));
            }
            mx0 = fmaxf(mx0, __shfl_xor_sync(0xffffffffu, mx0, 1));
            mx0 = fmaxf(mx0, __shfl_xor_sync(0xffffffffu, mx0, 2));
            mx1 = fmaxf(mx1, __shfl_xor_sync(0xffffffffu, mx1, 1));
            mx1 = fmaxf(mx1, __shfl_xor_sync(0xffffffffu, mx1, 2));
            const float mn0 = fmaxf(m0, mx0), mn1 = fmaxf(m1, mx1);
            const float c0 = __expf(m0 - mn0), c1 = __expf(m1 - mn1);
            float s0 = 0.f, s1 = 0.f;
#pragma unroll
            for (int j = 0; j < 8; ++j) {
                acc[j][0] = __expf(acc[j][0] - mn0); s0 += acc[j][0];
                acc[j][1] = __expf(acc[j][1] - mn0); s0 += acc[j][1];
                acc[j][2] = __expf(acc[j][2] - mn1); s1 += acc[j][2];
                acc[j][3] = __expf(acc[j][3] - mn1); s1 += acc[j][3];
            }
            s0 += __shfl_xor_sync(0xffffffffu, s0, 1);
            s0 += __shfl_xor_sync(0xffffffffu, s0, 2);
            s1 += __shfl_xor_sync(0xffffffffu, s1, 1);
            s1 += __shfl_xor_sync(0xffffffffu, s1, 2);
            l0 = l0 * c0 + s0; l1 = l1 * c1 + s1;
            m0 = mn0; m1 = mn1;
#pragma unroll
            for (int j = 0; j < 8; ++j) {
                O[j][0] *= c0; O[j][1] *= c0;
                O[j][2] *= c1; O[j][3] *= c1;
            }

#pragma unroll
            for (int t = 0; t < 4; ++t) {
                uint32_t aPh[4], aPl[4];
#pragma unroll
                for (int hf = 0; hf < 2; ++hf) {
                    const float* pv = acc[2 * t + hf];
                    __nv_bfloat16 h0 = __float2bfloat16(pv[0]);
                    __nv_bfloat16 h1 = __float2bfloat16(pv[1]);
                    __nv_bfloat16 h2 = __float2bfloat16(pv[2]);
                    __nv_bfloat16 h3 = __float2bfloat16(pv[3]);
                    aPh[hf * 2]     = pack2bf(h0, h1);
                    aPh[hf * 2 + 1] = pack2bf(h2, h3);
                    aPl[hf * 2]     = pack2bf(
                        __float2bfloat16(pv[0] - __bfloat162float(h0)),
                        __float2bfloat16(pv[1] - __bfloat162float(h1)));
                    aPl[hf * 2 + 1] = pack2bf(
                        __float2bfloat16(pv[2] - __bfloat162float(h2)),
                        __float2bfloat16(pv[3] - __bfloat162float(h3)));
                }
#pragma unroll
                for (int jp = 0; jp < 4; ++jp) {
                    uint32_t vH[4], vL[4];
                    const uint32_t vo = (uint32_t)((t * 16 + rT) * APITCH
                                                   + (jp * 2 + uT) * 16);
                    ldm4t(st + 2 * AKTILE + vo, vH);
                    mma_bf16(O[2 * jp],     aPh, vH[0], vH[2]);
                    mma_bf16(O[2 * jp + 1], aPh, vH[1], vH[3]);
                    mma_bf16(O[2 * jp],     aPl, vH[0], vH[2]);
                    mma_bf16(O[2 * jp + 1], aPl, vH[1], vH[3]);
                    ldm4t(st + 3 * AKTILE + vo, vL);
                    mma_bf16(O[2 * jp],     aPh, vL[0], vL[2]);
                    mma_bf16(O[2 * jp + 1], aPh, vL[1], vL[3]);
                }
            }
        }
        if (kb + 1 < nkb) cp_wait0();
        __syncthreads();
        buf ^= 1;
    }

    const float i0 = 1.f / l0, i1 = 1.f / l1;
    const size_t g0 = (rowQ0 + q0 + (lane >> 2)) * EE + h * DD;
    const size_t g1 = g0 + (size_t)8 * EE;
#pragma unroll
    for (int j = 0; j < 8; ++j) {
        const int col = j * 8 + ((lane & 3) << 1);
#pragma unroll
        for (int rr = 0; rr < 2; ++rr) {
            const float v0 = O[j][rr * 2] * (rr ? i1 : i0);
            const float v1 = O[j][rr * 2 + 1] * (rr ? i1 : i0);
            __nv_bfloat16 h0 = __float2bfloat16(v0);
            __nv_bfloat16 h1 = __float2bfloat16(v1);
            __nv_bfloat16 lo0 = __float2bfloat16(v0 - __bfloat162float(h0));
            __nv_bfloat16 lo1 = __float2bfloat16(v1 - __bfloat162float(h1));
            const size_t off = (rr ? g1 : g0) + col;
            *(uint32_t*)(ahi + off) = pack2bf(h0, h1);
            *(uint32_t*)(alo + off) = pack2bf(lo0, lo1);
        }
    }
}

// ---------------------------------------------------------------------------
extern "C" void kernel_launch(void* const* d_in, const int* in_sizes, int n_in,
                              void* d_out, int out_size)
{
    (void)in_sizes; (void)n_in; (void)out_size;
    const float* net_in = (const float*)d_in[0];
    const float* W_qkv  = (const float*)d_in[1];
    const float* W_out  = (const float*)d_in[2];
    float* outp = (float*)d_out;

    __nv_bfloat16 *xhi, *xlo, *wqhi, *wqlo, *wohi, *wolo, *qh, *ql, *ahi, *alo;
    cudaGetSymbolAddress((void**)&xhi,  g_xhi);
    cudaGetSymbolAddress((void**)&xlo,  g_xlo);
    cudaGetSymbolAddress((void**)&wqhi, g_wqhi);
    cudaGetSymbolAddress((void**)&wqlo, g_wqlo);
    cudaGetSymbolAddress((void**)&wohi, g_wohi);
    cudaGetSymbolAddress((void**)&wolo, g_wolo);
    cudaGetSymbolAddress((void**)&qh,   g_qkvhi);
    cudaGetSymbolAddress((void**)&ql,   g_qkvlo);
    cudaGetSymbolAddress((void**)&ahi,  g_ahi);
    cudaGetSymbolAddress((void**)&alo,  g_alo);

    cudaFuncSetAttribute(gemm3x,
                         cudaFuncAttributeMaxDynamicSharedMemorySize, GSMEM);
    cudaFuncSetAttribute(gemm_hyb,
                         cudaFuncAttributeMaxDynamicSharedMemorySize, HSMEM);
    cudaFuncSetAttribute(attn_tc,
                         cudaFuncAttributeMaxDynamicSharedMemorySize, ASMEM);

    // 0) input/weight splits
    {
        int n4 = (MM * EE) / 4;
        split_fp32<<<(n4 + 255) / 256, 256>>>(net_in, xhi, xlo, n4);
        n4 = (3 * EE * EE) / 4;
        split_fp32<<<(n4 + 255) / 256, 256>>>(W_qkv, wqhi, wqlo, n4);
        n4 = (EE * EE) / 4;
        split_fp32<<<(n4 + 255) / 256, 256>>>(W_out, wohi, wolo, n4);
    }

    // 1) QKV projection, hybrid tensor+fp32 -> split-bf16 qkv
    dim3 g1((3 * EE) / 192, MM / 128);        // 16 x 32
    gemm_hyb<<<g1, 384, HSMEM>>>(xhi, xlo, wqhi, wqlo, net_in, W_qkv,
                                 qh, ql, 3 * EE);

    // 2) Tensor-core causal flash attention -> split-bf16 activations
    dim3 ga(LL / QB, HH, BB);
    attn_tc<<<ga, 256, ASMEM>>>(qh, ql, ahi, alo);

    // 3) Output projection (pure tensor, R11) -> fp32 d_out
    dim3 g3(EE / 128, MM / 128);
    gemm3x<<<g3, 256, GSMEM>>>(ahi, alo, wohi, wolo, outp, EE);
}

// round 16
// speedup vs baseline: 1.0801x; 1.0691x over previous
#include <cuda_runtime.h>
#include <cuda_bf16.h>
#include <cstdint>

// Problem constants
#define BB   2
#define LL   2048
#define HH   16
#define DD   64
#define EE   1024
#define MM   (BB * LL)      /* 4096 rows */
#define QB   128
#define KVB  64

// Fused-GEMM smem geometry: K-chunk 64 bf16 (128 B/row), XOR swizzle.
// Tiles per stage: AH(128r)=16K, AL=16K, BH(64r)=8K, BL=8K  -> 48K/stage
#define FT_AH   0
#define FT_AL   16384
#define FT_BH   32768
#define FT_BL   40960
#define FSTG    49152
#define FSMEM   (2 * FSTG)             /* 98304 -> 2 CTAs/SM */

// Attention smem geometry (unchanged, validated)
#define APITCH  144
#define AKTILE  (64 * APITCH)
#define ASTAGE  (4 * AKTILE)
#define AQBYTES (2 * 128 * APITCH)
#define ASMEM   (AQBYTES + 2 * ASTAGE)

// ---------------------------------------------------------------------------
// Scratch (device globals — no runtime allocation allowed)
// ---------------------------------------------------------------------------
__device__ __nv_bfloat16 g_xhi[(size_t)MM * EE];
__device__ __nv_bfloat16 g_xlo[(size_t)MM * EE];
__device__ __nv_bfloat16 g_wqhi[(size_t)3 * EE * EE];
__device__ __nv_bfloat16 g_wqlo[(size_t)3 * EE * EE];
__device__ __nv_bfloat16 g_wohi[(size_t)EE * EE];
__device__ __nv_bfloat16 g_wolo[(size_t)EE * EE];
__device__ __nv_bfloat16 g_qkvhi[(size_t)MM * 3 * EE];
__device__ __nv_bfloat16 g_qkvlo[(size_t)MM * 3 * EE];
__device__ __nv_bfloat16 g_ahi[(size_t)MM * EE];
__device__ __nv_bfloat16 g_alo[(size_t)MM * EE];

// ---------------------------------------------------------------------------
// PTX helpers (baseline ISA only)
// ---------------------------------------------------------------------------
__device__ __forceinline__ uint32_t smem_u32(const void* p) {
    uint32_t a;
    asm("{ .reg .u64 t; cvta.to.shared.u64 t, %1; cvt.u32.u64 %0, t; }"
        : "=r"(a) : "l"(p));
    return a;
}
__device__ __forceinline__ void cp16(uint32_t saddr, const void* gaddr) {
    asm volatile("cp.async.cg.shared.global [%0], [%1], 16;"
                 :: "r"(saddr), "l"(gaddr) : "memory");
}
__device__ __forceinline__ void cp_commit() {
    asm volatile("cp.async.commit_group;" ::: "memory");
}
__device__ __forceinline__ void cp_wait1() {
    asm volatile("cp.async.wait_group 1;" ::: "memory");
}
__device__ __forceinline__ void cp_wait0() {
    asm volatile("cp.async.wait_group 0;" ::: "memory");
}
__device__ __forceinline__ void ldm4(uint32_t addr, uint32_t* r) {
    asm volatile("ldmatrix.sync.aligned.m8n8.x4.shared.b16 {%0,%1,%2,%3}, [%4];"
                 : "=r"(r[0]), "=r"(r[1]), "=r"(r[2]), "=r"(r[3]) : "r"(addr));
}
__device__ __forceinline__ void ldm4t(uint32_t addr, uint32_t* r) {
    asm volatile("ldmatrix.sync.aligned.m8n8.x4.trans.shared.b16 {%0,%1,%2,%3}, [%4];"
                 : "=r"(r[0]), "=r"(r[1]), "=r"(r[2]), "=r"(r[3]) : "r"(addr));
}
__device__ __forceinline__ void mma_bf16(float* c, const uint32_t* a,
                                         uint32_t b0, uint32_t b1) {
    asm volatile(
        "mma.sync.aligned.m16n8k16.row.col.f32.bf16.bf16.f32 "
        "{%0,%1,%2,%3}, {%4,%5,%6,%7}, {%8,%9}, {%0,%1,%2,%3};"
        : "+f"(c[0]), "+f"(c[1]), "+f"(c[2]), "+f"(c[3])
        : "r"(a[0]), "r"(a[1]), "r"(a[2]), "r"(a[3]), "r"(b0), "r"(b1));
}
__device__ __forceinline__ uint32_t pack2bf(__nv_bfloat16 x, __nv_bfloat16 y) {
    return (uint32_t)__bfloat16_as_ushort(x) |
           ((uint32_t)__bfloat16_as_ushort(y) << 16);
}

// ---------------------------------------------------------------------------
// fp32 -> (hi, lo) bf16 split
// ---------------------------------------------------------------------------
__global__ void split_fp32(const float* __restrict__ x, __nv_bfloat16* __restrict__ hi,
                           __nv_bfloat16* __restrict__ lo, int n4)
{
    int i = blockIdx.x * blockDim.x + threadIdx.x;
    if (i >= n4) return;
    float4 v = ((const float4*)x)[i];
    float f[4] = {v.x, v.y, v.z, v.w};
    uint32_t hb[4], lb[4];
#pragma unroll
    for (int j = 0; j < 4; ++j) {
        __nv_bfloat16 h = __float2bfloat16(f[j]);
        float r = f[j] - __bfloat162float(h);
        __nv_bfloat16 l = __float2bfloat16(r);
        hb[j] = (uint32_t)__bfloat16_as_ushort(h);
        lb[j] = (uint32_t)__bfloat16_as_ushort(l);
    }
    ((uint2*)hi)[i] = make_uint2(hb[0] | (hb[1] << 16), hb[2] | (hb[3] << 16));
    ((uint2*)lo)[i] = make_uint2(lb[0] | (lb[1] << 16), lb[2] | (lb[3] << 16));
}

// ---------------------------------------------------------------------------
// Fused 3-split mma.sync GEMM, 2 CTAs/SM: C = A[M,K]*B[N,K]^T.
// CTA tile 128x64, 8 warps (4m x 2n), warp tile 32x32.
// Per 64-K chunk: stage AH,AL,BH,BL once; 3 mma passes (hh, lh, hl).
// 2-stage cp.async pipeline (48KB/stage), XOR-swizzled 128B pitch.
// Output: fp32 (Cf) or split-bf16 (Chi/Clo).
// ---------------------------------------------------------------------------
__global__ __launch_bounds__(256, 2)
void gemm3f(const __nv_bfloat16* __restrict__ Ahi, const __nv_bfloat16* __restrict__ Alo,
            const __nv_bfloat16* __restrict__ Bhi, const __nv_bfloat16* __restrict__ Blo,
            float* __restrict__ Cf, __nv_bfloat16* __restrict__ Chi,
            __nv_bfloat16* __restrict__ Clo, int N)
{
    extern __shared__ __align__(16) char smraw[];
    const uint32_t sbase = smem_u32(smraw);

    const int tid  = threadIdx.x;
    const int wid  = tid >> 5;
    const int lane = tid & 31;
    const int m0   = blockIdx.y * 128;
    const int n0   = blockIdx.x * 64;

    // warp compute mapping: 4m x 2n, warp tile 32x32
    const int wm = wid & 3;               // m quarter: rows wm*32..+32
    const int wn = wid >> 2;              // n half:    cols wn*32..+32
    uint32_t arow[2], aswr[2];
#pragma unroll
    for (int i = 0; i < 2; ++i) {
        const int r = wm * 32 + i * 16 + (lane & 15);
        arow[i] = (uint32_t)(r * 128);
        aswr[i] = (uint32_t)((r & 7) << 4);
    }
    uint32_t brow[2], bswr[2];
#pragma unroll
    for (int jp = 0; jp < 2; ++jp) {
        const int r = wn * 32 + jp * 16 + (lane & 15);
        brow[jp] = (uint32_t)(r * 128);
        bswr[jp] = (uint32_t)((r & 7) << 4);
    }
    const uint32_t ubase = (uint32_t)((lane >> 4) * 16);

    float acc[2][4][4];
#pragma unroll
    for (int i = 0; i < 2; ++i)
#pragma unroll
        for (int j = 0; j < 4; ++j)
#pragma unroll
            for (int v = 0; v < 4; ++v) acc[i][j][v] = 0.f;

    // loader: 3072 cp16 slots/stage, 12 per thread
    auto issue = [&](int c, int stage) {
        const int k0 = c * 64;
        const uint32_t so = sbase + (uint32_t)(stage * FSTG);
#pragma unroll
        for (int q = 0; q < 12; ++q) {
            const int s  = tid + (q << 8);      // 0..3071
            const int t8 = s >> 3;              // 0..383
            const int u  = s & 7;
            const __nv_bfloat16* gb;
            int row; uint32_t tb;
            if (t8 < 128)      { gb = Ahi; row = t8;       tb = FT_AH; }
            else if (t8 < 256) { gb = Alo; row = t8 - 128; tb = FT_AL; }
            else if (t8 < 320) { gb = Bhi; row = t8 - 256; tb = FT_BH; }
            else               { gb = Blo; row = t8 - 320; tb = FT_BL; }
            const int grow = (t8 < 256 ? m0 : n0) + row;
            const uint32_t sw = (uint32_t)(((u * 16) ^ ((row & 7) << 4)) + row * 128);
            cp16(so + tb + sw, gb + (size_t)grow * EE + k0 + u * 8);
        }
        cp_commit();
    };

    issue(0, 0);

    int buf = 0;
    for (int c = 0; c < 16; ++c) {
        if (c + 1 < 16) { issue(c + 1, buf ^ 1); cp_wait1(); }
        else cp_wait0();
        __syncthreads();                       // chunk c visible to all

        const uint32_t sb = sbase + (uint32_t)(buf * FSTG);
#pragma unroll
        for (int ks = 0; ks < 4; ++ks) {
            const uint32_t cb = ubase + (uint32_t)(ks * 32);
            uint32_t aH[2][4], aL[2][4], bH[2][4], bL[2][4];
#pragma unroll
            for (int i = 0; i < 2; ++i) {
                const uint32_t ao = arow[i] + (cb ^ aswr[i]);
                ldm4(sb + FT_AH + ao, aH[i]);
                ldm4(sb + FT_AL + ao, aL[i]);
            }
#pragma unroll
            for (int jp = 0; jp < 2; ++jp) {
                const uint32_t bo = brow[jp] + (cb ^ bswr[jp]);
                ldm4(sb + FT_BH + bo, bH[jp]);
                ldm4(sb + FT_BL + bo, bL[jp]);
            }
#pragma unroll
            for (int i = 0; i < 2; ++i)
#pragma unroll
                for (int j = 0; j < 4; ++j) {
                    const int jp = j >> 1, od = j & 1;
                    mma_bf16(acc[i][j], aH[i], bH[jp][od], bH[jp][od + 2]);
                    mma_bf16(acc[i][j], aL[i], bH[jp][od], bH[jp][od + 2]);
                    mma_bf16(acc[i][j], aH[i], bL[jp][od], bL[jp][od + 2]);
                }
        }
        __syncthreads();                       // all reads of buf done
        buf ^= 1;
    }

    const int gr  = lane >> 2;
    const int gc2 = (lane & 3) * 2;
#pragma unroll
    for (int i = 0; i < 2; ++i) {
        const int row = m0 + wm * 32 + i * 16 + gr;
#pragma unroll
        for (int j = 0; j < 4; ++j) {
            const int col = n0 + wn * 32 + j * 8 + gc2;
            if (Cf) {
                *(float2*)(Cf + (size_t)row * N + col) =
                    make_float2(acc[i][j][0], acc[i][j][1]);
                *(float2*)(Cf + (size_t)(row + 8) * N + col) =
                    make_float2(acc[i][j][2], acc[i][j][3]);
            } else {
#pragma unroll
                for (int rr = 0; rr < 2; ++rr) {
                    float v0 = acc[i][j][rr * 2], v1 = acc[i][j][rr * 2 + 1];
                    __nv_bfloat16 h0 = __float2bfloat16(v0);
                    __nv_bfloat16 h1 = __float2bfloat16(v1);
                    __nv_bfloat16 l0 = __float2bfloat16(v0 - __bfloat162float(h0));
                    __nv_bfloat16 l1 = __float2bfloat16(v1 - __bfloat162float(h1));
                    const size_t off = (size_t)(row + rr * 8) * N + col;
                    *(uint32_t*)(Chi + off) = pack2bf(h0, h1);
                    *(uint32_t*)(Clo + off) = pack2bf(l0, l1);
                }
            }
        }
    }
}

// ---------------------------------------------------------------------------
// Tensor-core flash attention, causal, bf16 3-split (unchanged; validated).
// ---------------------------------------------------------------------------
__global__ __launch_bounds__(256, 2)
void attn_tc(const __nv_bfloat16* __restrict__ qkvh,
             const __nv_bfloat16* __restrict__ qkvl,
             __nv_bfloat16* __restrict__ ahi, __nv_bfloat16* __restrict__ alo)
{
    extern __shared__ __align__(16) char smA[];
    const uint32_t sQ  = smem_u32(smA);
    const uint32_t sKV = sQ + AQBYTES;

    const int tid  = threadIdx.x;
    const int wid  = tid >> 5;
    const int lane = tid & 31;
    const int qb   = (int)gridDim.x - 1 - (int)blockIdx.x;
    const int h    = blockIdx.y;
    const int b    = blockIdx.z;

    const size_t rowQ0 = (size_t)(b * LL + qb * QB);
    const size_t rowB  = (size_t)(b * LL);

#pragma unroll
    for (int i = 0; i < 8; ++i) {
        int s = tid + (i << 8);
        int half = s >> 10;
        int row  = (s >> 3) & 127;
        int u    = s & 7;
        const __nv_bfloat16* src = (half ? qkvl : qkvh)
            + (rowQ0 + row) * (3 * EE) + h * DD + u * 8;
        cp16(sQ + half * 18432 + row * APITCH + u * 16, src);
    }
    auto issue_kv = [&](int kb, uint32_t dst) {
#pragma unroll
        for (int i = 0; i < 8; ++i) {
            int s = tid + (i << 8);
            int tn  = s >> 9;
            int row = (s >> 3) & 63;
            int u   = s & 7;
            const __nv_bfloat16* base = (tn & 1) ? qkvl : qkvh;
            int col = ((tn >> 1) ? 2 * EE : EE) + h * DD + u * 8;
            cp16(dst + tn * AKTILE + row * APITCH + u * 16,
                 base + (rowB + (size_t)kb * KVB + row) * (3 * EE) + col);
        }
    };
    issue_kv(0, sKV);
    cp_commit();
    cp_wait0();
    __syncthreads();

    const int q0   = wid * 16;
    const int qmin = qb * QB + q0;
    const int rA = lane & 15, uA = (lane >> 4);
    const int rT = (lane & 7) + ((lane >> 4) << 3);
    const int uT = (lane >> 3) & 1;

    float m0 = -1e30f, m1 = -1e30f, l0 = 0.f, l1 = 0.f;
    float O[8][4];
#pragma unroll
    for (int j = 0; j < 8; ++j)
#pragma unroll
        for (int v = 0; v < 4; ++v) O[j][v] = 0.f;

    const int nkb = 2 * qb + 2;
    int buf = 0;
    for (int kb = 0; kb < nkb; ++kb) {
        if (kb + 1 < nkb) { issue_kv(kb + 1, sKV + (buf ^ 1) * ASTAGE); cp_commit(); }
        const uint32_t st = sKV + buf * ASTAGE;
        const bool skip = (kb * KVB > qmin + 15);
        if (!skip) {
            float acc[8][4];
#pragma unroll
            for (int j = 0; j < 8; ++j)
#pragma unroll
                for (int v = 0; v < 4; ++v) acc[j][v] = 0.f;

#pragma unroll
            for (int ks = 0; ks < 4; ++ks) {
                uint32_t aH[4], aL[4];
                ldm4(sQ + (q0 + rA) * APITCH + uA * 16 + ks * 32, aH);
                ldm4(sQ + 18432 + (q0 + rA) * APITCH + uA * 16 + ks * 32, aL);
#pragma unroll
                for (int jp = 0; jp < 4; ++jp) {
                    uint32_t bH[4], bL[4];
                    const uint32_t ko = (uint32_t)((jp * 16 + rA) * APITCH + uA * 16 + ks * 32);
                    ldm4(st + ko, bH);
                    mma_bf16(acc[2 * jp],     aH, bH[0], bH[2]);
                    mma_bf16(acc[2 * jp + 1], aH, bH[1], bH[3]);
                    mma_bf16(acc[2 * jp],     aL, bH[0], bH[2]);
                    mma_bf16(acc[2 * jp + 1], aL, bH[1], bH[3]);
                    ldm4(st + AKTILE + ko, bL);
                    mma_bf16(acc[2 * jp],     aH, bL[0], bL[2]);
                    mma_bf16(acc[2 * jp + 1], aH, bL[1], bL[3]);
                }
            }

            const int r0 = qmin + (lane >> 2), r1 = r0 + 8;
            const bool needmask = (kb * KVB + KVB - 1 > qmin);
#pragma unroll
            for (int j = 0; j < 8; ++j) {
                acc[j][0] *= 0.125f; acc[j][1] *= 0.125f;
                acc[j][2] *= 0.125f; acc[j][3] *= 0.125f;
                if (needmask) {
                    const int key = kb * KVB + j * 8 + ((lane & 3) << 1);
                    if (key     > r0) acc[j][0] = -1e30f;
                    if (key + 1 > r0) acc[j][1] = -1e30f;
                    if (key     > r1) acc[j][2] = -1e30f;
                    if (key + 1 > r1) acc[j][3] = -1e30f;
                }
            }

            float mx0 = -1e30f, mx1 = -1e30f;
#pragma unroll
            for (int j = 0; j < 8; ++j) {
                mx0 = fmaxf(mx0, fmaxf(acc[j][0], acc[j][1]));
                mx1 = fmaxf(mx1, fmaxf(acc[j][2], acc[j][3]));
            }
            mx0 = fmaxf(mx0, __shfl_xor_sync(0xffffffffu, mx0, 1));
            mx0 = fmaxf(mx0, __shfl_xor_sync(0xffffffffu, mx0, 2));
            mx1 = fmaxf(mx1, __shfl_xor_sync(0xffffffffu, mx1, 1));
            mx1 = fmaxf(mx1, __shfl_xor_sync(0xffffffffu, mx1, 2));
            const float mn0 = fmaxf(m0, mx0), mn1 = fmaxf(m1, mx1);
            const float c0 = __expf(m0 - mn0), c1 = __expf(m1 - mn1);
            float s0 = 0.f, s1 = 0.f;
#pragma unroll
            for (int j = 0; j < 8; ++j) {
                acc[j][0] = __expf(acc[j][0] - mn0); s0 += acc[j][0];
                acc[j][1] = __expf(acc[j][1] - mn0); s0 += acc[j][1];
                acc[j][2] = __expf(acc[j][2] - mn1); s1 += acc[j][2];
                acc[j][3] = __expf(acc[j][3] - mn1); s1 += acc[j][3];
            }
            s0 += __shfl_xor_sync(0xffffffffu, s0, 1);
            s0 += __shfl_xor_sync(0xffffffffu, s0, 2);
            s1 += __shfl_xor_sync(0xffffffffu, s1, 1);
            s1 += __shfl_xor_sync(0xffffffffu, s1, 2);
            l0 = l0 * c0 + s0; l1 = l1 * c1 + s1;
            m0 = mn0; m1 = mn1;
#pragma unroll
            for (int j = 0; j < 8; ++j) {
                O[j][0] *= c0; O[j][1] *= c0;
                O[j][2] *= c1; O[j][3] *= c1;
            }

#pragma unroll
            for (int t = 0; t < 4; ++t) {
                uint32_t aPh[4], aPl[4];
#pragma unroll
                for (int hf = 0; hf < 2; ++hf) {
                    const float* pv = acc[2 * t + hf];
                    __nv_bfloat16 h0 = __float2bfloat16(pv[0]);
                    __nv_bfloat16 h1 = __float2bfloat16(pv[1]);
                    __nv_bfloat16 h2 = __float2bfloat16(pv[2]);
                    __nv_bfloat16 h3 = __float2bfloat16(pv[3]);
                    aPh[hf * 2]     = pack2bf(h0, h1);
                    aPh[hf * 2 + 1] = pack2bf(h2, h3);
                    aPl[hf * 2]     = pack2bf(
                        __float2bfloat16(pv[0] - __bfloat162float(h0)),
                        __float2bfloat16(pv[1] - __bfloat162float(h1)));
                    aPl[hf * 2 + 1] = pack2bf(
                        __float2bfloat16(pv[2] - __bfloat162float(h2)),
                        __float2bfloat16(pv[3] - __bfloat162float(h3)));
                }
#pragma unroll
                for (int jp = 0; jp < 4; ++jp) {
                    uint32_t vH[4], vL[4];
                    const uint32_t vo = (uint32_t)((t * 16 + rT) * APITCH
                                                   + (jp * 2 + uT) * 16);
                    ldm4t(st + 2 * AKTILE + vo, vH);
                    mma_bf16(O[2 * jp],     aPh, vH[0], vH[2]);
                    mma_bf16(O[2 * jp + 1], aPh, vH[1], vH[3]);
                    mma_bf16(O[2 * jp],     aPl, vH[0], vH[2]);
                    mma_bf16(O[2 * jp + 1], aPl, vH[1], vH[3]);
                    ldm4t(st + 3 * AKTILE + vo, vL);
                    mma_bf16(O[2 * jp],     aPh, vL[0], vL[2]);
                    mma_bf16(O[2 * jp + 1], aPh, vL[1], vL[3]);
                }
            }
        }
        if (kb + 1 < nkb) cp_wait0();
        __syncthreads();
        buf ^= 1;
    }

    const float i0 = 1.f / l0, i1 = 1.f / l1;
    const size_t g0 = (rowQ0 + q0 + (lane >> 2)) * EE + h * DD;
    const size_t g1 = g0 + (size_t)8 * EE;
#pragma unroll
    for (int j = 0; j < 8; ++j) {
        const int col = j * 8 + ((lane & 3) << 1);
#pragma unroll
        for (int rr = 0; rr < 2; ++rr) {
            const float v0 = O[j][rr * 2] * (rr ? i1 : i0);
            const float v1 = O[j][rr * 2 + 1] * (rr ? i1 : i0);
            __nv_bfloat16 h0 = __float2bfloat16(v0);
            __nv_bfloat16 h1 = __float2bfloat16(v1);
            __nv_bfloat16 lo0 = __float2bfloat16(v0 - __bfloat162float(h0));
            __nv_bfloat16 lo1 = __float2bfloat16(v1 - __bfloat162float(h1));
            const size_t off = (rr ? g1 : g0) + col;
            *(uint32_t*)(ahi + off) = pack2bf(h0, h1);
            *(uint32_t*)(alo + off) = pack2bf(lo0, lo1);
        }
    }
}

// ---------------------------------------------------------------------------
extern "C" void kernel_launch(void* const* d_in, const int* in_sizes, int n_in,
                              void* d_out, int out_size)
{
    (void)in_sizes; (void)n_in; (void)out_size;
    const float* net_in = (const float*)d_in[0];
    const float* W_qkv  = (const float*)d_in[1];
    const float* W_out  = (const float*)d_in[2];
    float* outp = (float*)d_out;

    __nv_bfloat16 *xhi, *xlo, *wqhi, *wqlo, *wohi, *wolo, *qh, *ql, *ahi, *alo;
    cudaGetSymbolAddress((void**)&xhi,  g_xhi);
    cudaGetSymbolAddress((void**)&xlo,  g_xlo);
    cudaGetSymbolAddress((void**)&wqhi, g_wqhi);
    cudaGetSymbolAddress((void**)&wqlo, g_wqlo);
    cudaGetSymbolAddress((void**)&wohi, g_wohi);
    cudaGetSymbolAddress((void**)&wolo, g_wolo);
    cudaGetSymbolAddress((void**)&qh,   g_qkvhi);
    cudaGetSymbolAddress((void**)&ql,   g_qkvlo);
    cudaGetSymbolAddress((void**)&ahi,  g_ahi);
    cudaGetSymbolAddress((void**)&alo,  g_alo);

    cudaFuncSetAttribute(gemm3f,
                         cudaFuncAttributeMaxDynamicSharedMemorySize, FSMEM);
    cudaFuncSetAttribute(attn_tc,
                         cudaFuncAttributeMaxDynamicSharedMemorySize, ASMEM);

    // 0) input/weight splits
    {
        int n4 = (MM * EE) / 4;
        split_fp32<<<(n4 + 255) / 256, 256>>>(net_in, xhi, xlo, n4);
        n4 = (3 * EE * EE) / 4;
        split_fp32<<<(n4 + 255) / 256, 256>>>(W_qkv, wqhi, wqlo, n4);
        n4 = (EE * EE) / 4;
        split_fp32<<<(n4 + 255) / 256, 256>>>(W_out, wohi, wolo, n4);
    }

    // 1) QKV projection -> split-bf16 qkv
    dim3 g1((3 * EE) / 64, MM / 128);          // 48 x 32
    gemm3f<<<g1, 256, FSMEM>>>(xhi, xlo, wqhi, wqlo, nullptr, qh, ql, 3 * EE);

    // 2) Tensor-core causal flash attention -> split-bf16 activations
    dim3 ga(LL / QB, HH, BB);
    attn_tc<<<ga, 256, ASMEM>>>(qh, ql, ahi, alo);

    // 3) Output projection -> fp32 d_out
    dim3 g3(EE / 64, MM / 128);                // 16 x 32
    gemm3f<<<g3, 256, FSMEM>>>(ahi, alo, wohi, wolo, outp, nullptr, nullptr, EE);
}

// round 17
// speedup vs baseline: 1.5132x; 1.4011x over previous
#include <cuda_runtime.h>
#include <cuda_bf16.h>
#include <cstdint>

// Problem constants
#define BB   2
#define LL   2048
#define HH   16
#define DD   64
#define EE   1024
#define MM   (BB * LL)      /* 4096 rows */
#define QB   128
#define KVB  64

// gemm3f smem geometry: K-chunk 64 bf16 (128 B/row), XOR swizzle.
// Tiles per stage: AH(128r)=16K, AL=16K, BH(64r)=8K, BL=8K -> 48K/stage
#define FT_AH   0
#define FT_AL   16384
#define FT_BH   32768
#define FT_BL   40960
#define FSTG    49152
#define FSMEM   (2 * FSTG)             /* 98304 -> 2 CTAs/SM */

// gemm3x smem geometry (R11): K-chunk 64 bf16, 144B pitch, 3 stages
#define GROWB   144
#define GTILEB  (128 * GROWB)
#define GBUFB   (2 * GTILEB)
#define GSMEM   (3 * GBUFB)            /* 110592 */

// Attention smem geometry (unchanged, validated)
#define APITCH  144
#define AKTILE  (64 * APITCH)
#define ASTAGE  (4 * AKTILE)
#define AQBYTES (2 * 128 * APITCH)
#define ASMEM   (AQBYTES + 2 * ASTAGE)

// ---------------------------------------------------------------------------
// Scratch (device globals — no runtime allocation allowed)
// ---------------------------------------------------------------------------
__device__ __nv_bfloat16 g_xhi[(size_t)MM * EE];
__device__ __nv_bfloat16 g_xlo[(size_t)MM * EE];
__device__ __nv_bfloat16 g_wqhi[(size_t)3 * EE * EE];
__device__ __nv_bfloat16 g_wqlo[(size_t)3 * EE * EE];
__device__ __nv_bfloat16 g_wohi[(size_t)EE * EE];
__device__ __nv_bfloat16 g_wolo[(size_t)EE * EE];
__device__ __nv_bfloat16 g_qkvhi[(size_t)MM * 3 * EE];
__device__ __nv_bfloat16 g_qkvlo[(size_t)MM * 3 * EE];
__device__ __nv_bfloat16 g_ahi[(size_t)MM * EE];
__device__ __nv_bfloat16 g_alo[(size_t)MM * EE];

// ---------------------------------------------------------------------------
// PTX helpers (baseline ISA only)
// ---------------------------------------------------------------------------
__device__ __forceinline__ uint32_t smem_u32(const void* p) {
    uint32_t a;
    asm("{ .reg .u64 t; cvta.to.shared.u64 t, %1; cvt.u32.u64 %0, t; }"
        : "=r"(a) : "l"(p));
    return a;
}
__device__ __forceinline__ void cp16(uint32_t saddr, const void* gaddr) {
    asm volatile("cp.async.cg.shared.global [%0], [%1], 16;"
                 :: "r"(saddr), "l"(gaddr) : "memory");
}
__device__ __forceinline__ void cp_commit() {
    asm volatile("cp.async.commit_group;" ::: "memory");
}
__device__ __forceinline__ void cp_wait1() {
    asm volatile("cp.async.wait_group 1;" ::: "memory");
}
__device__ __forceinline__ void cp_wait0() {
    asm volatile("cp.async.wait_group 0;" ::: "memory");
}
__device__ __forceinline__ void ldm4(uint32_t addr, uint32_t* r) {
    asm volatile("ldmatrix.sync.aligned.m8n8.x4.shared.b16 {%0,%1,%2,%3}, [%4];"
                 : "=r"(r[0]), "=r"(r[1]), "=r"(r[2]), "=r"(r[3]) : "r"(addr));
}
__device__ __forceinline__ void ldm4t(uint32_t addr, uint32_t* r) {
    asm volatile("ldmatrix.sync.aligned.m8n8.x4.trans.shared.b16 {%0,%1,%2,%3}, [%4];"
                 : "=r"(r[0]), "=r"(r[1]), "=r"(r[2]), "=r"(r[3]) : "r"(addr));
}
__device__ __forceinline__ void mma_bf16(float* c, const uint32_t* a,
                                         uint32_t b0, uint32_t b1) {
    asm volatile(
        "mma.sync.aligned.m16n8k16.row.col.f32.bf16.bf16.f32 "
        "{%0,%1,%2,%3}, {%4,%5,%6,%7}, {%8,%9}, {%0,%1,%2,%3};"
        : "+f"(c[0]), "+f"(c[1]), "+f"(c[2]), "+f"(c[3])
        : "r"(a[0]), "r"(a[1]), "r"(a[2]), "r"(a[3]), "r"(b0), "r"(b1));
}
__device__ __forceinline__ uint32_t pack2bf(__nv_bfloat16 x, __nv_bfloat16 y) {
    return (uint32_t)__bfloat16_as_ushort(x) |
           ((uint32_t)__bfloat16_as_ushort(y) << 16);
}

// ---------------------------------------------------------------------------
// fp32 -> (hi, lo) bf16 split
// ---------------------------------------------------------------------------
__global__ void split_fp32(const float* __restrict__ x, __nv_bfloat16* __restrict__ hi,
                           __nv_bfloat16* __restrict__ lo, int n4)
{
    int i = blockIdx.x * blockDim.x + threadIdx.x;
    if (i >= n4) return;
    float4 v = ((const float4*)x)[i];
    float f[4] = {v.x, v.y, v.z, v.w};
    uint32_t hb[4], lb[4];
#pragma unroll
    for (int j = 0; j < 4; ++j) {
        __nv_bfloat16 h = __float2bfloat16(f[j]);
        float r = f[j] - __bfloat162float(h);
        __nv_bfloat16 l = __float2bfloat16(r);
        hb[j] = (uint32_t)__bfloat16_as_ushort(h);
        lb[j] = (uint32_t)__bfloat16_as_ushort(l);
    }
    ((uint2*)hi)[i] = make_uint2(hb[0] | (hb[1] << 16), hb[2] | (hb[3] << 16));
    ((uint2*)lo)[i] = make_uint2(lb[0] | (lb[1] << 16), lb[2] | (lb[3] << 16));
}

// ---------------------------------------------------------------------------
// gemm3f (R16, validated on QKV): fused 3-split, CTA tile 128x64, 2 CTAs/SM.
// Used ONLY for the big QKV GEMM (>=5 waves).
// ---------------------------------------------------------------------------
__global__ __launch_bounds__(256, 2)
void gemm3f(const __nv_bfloat16* __restrict__ Ahi, const __nv_bfloat16* __restrict__ Alo,
            const __nv_bfloat16* __restrict__ Bhi, const __nv_bfloat16* __restrict__ Blo,
            __nv_bfloat16* __restrict__ Chi, __nv_bfloat16* __restrict__ Clo, int N)
{
    extern __shared__ __align__(16) char smraw[];
    const uint32_t sbase = smem_u32(smraw);

    const int tid  = threadIdx.x;
    const int wid  = tid >> 5;
    const int lane = tid & 31;
    const int m0   = blockIdx.y * 128;
    const int n0   = blockIdx.x * 64;

    const int wm = wid & 3;
    const int wn = wid >> 2;
    uint32_t arow[2], aswr[2];
#pragma unroll
    for (int i = 0; i < 2; ++i) {
        const int r = wm * 32 + i * 16 + (lane & 15);
        arow[i] = (uint32_t)(r * 128);
        aswr[i] = (uint32_t)((r & 7) << 4);
    }
    uint32_t brow[2], bswr[2];
#pragma unroll
    for (int jp = 0; jp < 2; ++jp) {
        const int r = wn * 32 + jp * 16 + (lane & 15);
        brow[jp] = (uint32_t)(r * 128);
        bswr[jp] = (uint32_t)((r & 7) << 4);
    }
    const uint32_t ubase = (uint32_t)((lane >> 4) * 16);

    float acc[2][4][4];
#pragma unroll
    for (int i = 0; i < 2; ++i)
#pragma unroll
        for (int j = 0; j < 4; ++j)
#pragma unroll
            for (int v = 0; v < 4; ++v) acc[i][j][v] = 0.f;

    auto issue = [&](int c, int stage) {
        const int k0 = c * 64;
        const uint32_t so = sbase + (uint32_t)(stage * FSTG);
#pragma unroll
        for (int q = 0; q < 12; ++q) {
            const int s  = tid + (q << 8);
            const int t8 = s >> 3;
            const int u  = s & 7;
            const __nv_bfloat16* gb;
            int row; uint32_t tb;
            if (t8 < 128)      { gb = Ahi; row = t8;       tb = FT_AH; }
            else if (t8 < 256) { gb = Alo; row = t8 - 128; tb = FT_AL; }
            else if (t8 < 320) { gb = Bhi; row = t8 - 256; tb = FT_BH; }
            else               { gb = Blo; row = t8 - 320; tb = FT_BL; }
            const int grow = (t8 < 256 ? m0 : n0) + row;
            const uint32_t sw = (uint32_t)(((u * 16) ^ ((row & 7) << 4)) + row * 128);
            cp16(so + tb + sw, gb + (size_t)grow * EE + k0 + u * 8);
        }
        cp_commit();
    };

    issue(0, 0);

    int buf = 0;
    for (int c = 0; c < 16; ++c) {
        if (c + 1 < 16) { issue(c + 1, buf ^ 1); cp_wait1(); }
        else cp_wait0();
        __syncthreads();

        const uint32_t sb = sbase + (uint32_t)(buf * FSTG);
#pragma unroll
        for (int ks = 0; ks < 4; ++ks) {
            const uint32_t cb = ubase + (uint32_t)(ks * 32);
            uint32_t aH[2][4], aL[2][4], bH[2][4], bL[2][4];
#pragma unroll
            for (int i = 0; i < 2; ++i) {
                const uint32_t ao = arow[i] + (cb ^ aswr[i]);
                ldm4(sb + FT_AH + ao, aH[i]);
                ldm4(sb + FT_AL + ao, aL[i]);
            }
#pragma unroll
            for (int jp = 0; jp < 2; ++jp) {
                const uint32_t bo = brow[jp] + (cb ^ bswr[jp]);
                ldm4(sb + FT_BH + bo, bH[jp]);
                ldm4(sb + FT_BL + bo, bL[jp]);
            }
#pragma unroll
            for (int i = 0; i < 2; ++i)
#pragma unroll
                for (int j = 0; j < 4; ++j) {
                    const int jp = j >> 1, od = j & 1;
                    mma_bf16(acc[i][j], aH[i], bH[jp][od], bH[jp][od + 2]);
                    mma_bf16(acc[i][j], aL[i], bH[jp][od], bH[jp][od + 2]);
                    mma_bf16(acc[i][j], aH[i], bL[jp][od], bL[jp][od + 2]);
                }
        }
        __syncthreads();
        buf ^= 1;
    }

    const int gr  = lane >> 2;
    const int gc2 = (lane & 3) * 2;
#pragma unroll
    for (int i = 0; i < 2; ++i) {
        const int row = m0 + wm * 32 + i * 16 + gr;
#pragma unroll
        for (int j = 0; j < 4; ++j) {
            const int col = n0 + wn * 32 + j * 8 + gc2;
#pragma unroll
            for (int rr = 0; rr < 2; ++rr) {
                float v0 = acc[i][j][rr * 2], v1 = acc[i][j][rr * 2 + 1];
                __nv_bfloat16 h0 = __float2bfloat16(v0);
                __nv_bfloat16 h1 = __float2bfloat16(v1);
                __nv_bfloat16 l0 = __float2bfloat16(v0 - __bfloat162float(h0));
                __nv_bfloat16 l1 = __float2bfloat16(v1 - __bfloat162float(h1));
                const size_t off = (size_t)(row + rr * 8) * N + col;
                *(uint32_t*)(Chi + off) = pack2bf(h0, h1);
                *(uint32_t*)(Clo + off) = pack2bf(l0, l1);
            }
        }
    }
}

// ---------------------------------------------------------------------------
// gemm3x (R11/R14, validated): 3-phase 3-split, CTA tile 128x128, 3-stage.
// Used ONLY for the small output projection (<1 wave with 256 CTAs).
// ---------------------------------------------------------------------------
__global__ __launch_bounds__(256, 2)
void gemm3x(const __nv_bfloat16* __restrict__ Ahi, const __nv_bfloat16* __restrict__ Alo,
            const __nv_bfloat16* __restrict__ Bhi, const __nv_bfloat16* __restrict__ Blo,
            float* __restrict__ Cf, int N)
{
    extern __shared__ __align__(16) char smraw[];
    const uint32_t sbase = smem_u32(smraw);

    const int tid  = threadIdx.x;
    const int wid  = tid >> 5;
    const int lane = tid & 31;
    const int m0   = blockIdx.y * 128;
    const int n0   = blockIdx.x * 128;

    const int lr = tid >> 1;
    const int lh = tid & 1;
    const uint32_t sArow = (uint32_t)(lr * GROWB + lh * 64);
    const uint32_t sBrow = sArow + GTILEB;
    const size_t gAoff = (size_t)(m0 + lr) * EE + lh * 32;
    const size_t gBoff = (size_t)(n0 + lr) * EE + lh * 32;

    const int wm = wid & 1;
    const int wn = wid >> 1;
    uint32_t aoff[4], boff[2];
#pragma unroll
    for (int i = 0; i < 4; ++i)
        aoff[i] = (uint32_t)((wm * 64 + i * 16 + (lane & 15)) * GROWB + (lane >> 4) * 16);
#pragma unroll
    for (int jp = 0; jp < 2; ++jp)
        boff[jp] = (uint32_t)(GTILEB + (wn * 32 + jp * 16 + (lane & 15)) * GROWB
                              + (lane >> 4) * 16);

    float acc[4][4][4];
#pragma unroll
    for (int i = 0; i < 4; ++i)
#pragma unroll
        for (int j = 0; j < 4; ++j)
#pragma unroll
            for (int v = 0; v < 4; ++v) acc[i][j][v] = 0.f;

    auto issue = [&](int c, int stage) {
        const int ph = c >> 4;
        const int k0 = (c & 15) * 64;
        const __nv_bfloat16* ga = ((ph == 1) ? Alo : Ahi) + gAoff + k0;
        const __nv_bfloat16* gb = ((ph == 2) ? Blo : Bhi) + gBoff + k0;
        const uint32_t so = sbase + (uint32_t)(stage * GBUFB);
#pragma unroll
        for (int q = 0; q < 4; ++q) {
            cp16(so + sArow + q * 16, ga + q * 8);
            cp16(so + sBrow + q * 16, gb + q * 8);
        }
        cp_commit();
    };

    issue(0, 0);
    issue(1, 1);

    int stage = 0;
    for (int c = 0; c < 48; ++c) {
        if (c + 1 < 48) cp_wait1(); else cp_wait0();
        __syncthreads();
        if (c + 2 < 48) issue(c + 2, (stage + 2) % 3);

        const uint32_t sb = sbase + (uint32_t)(stage * GBUFB);
#pragma unroll
        for (int ks = 0; ks < 4; ++ks) {
            uint32_t af[4][4], bfr[2][4];
#pragma unroll
            for (int i = 0; i < 4; ++i) ldm4(sb + aoff[i] + ks * 32, af[i]);
#pragma unroll
            for (int jp = 0; jp < 2; ++jp) ldm4(sb + boff[jp] + ks * 32, bfr[jp]);
#pragma unroll
            for (int i = 0; i < 4; ++i)
#pragma unroll
                for (int j = 0; j < 4; ++j) {
                    const int jp = j >> 1, od = j & 1;
                    mma_bf16(acc[i][j], af[i], bfr[jp][od], bfr[jp][od + 2]);
                }
        }
        stage = (stage + 1) % 3;
    }

    const int gr  = lane >> 2;
    const int gc2 = (lane & 3) * 2;
#pragma unroll
    for (int i = 0; i < 4; ++i) {
        const int row = m0 + wm * 64 + i * 16 + gr;
#pragma unroll
        for (int j = 0; j < 4; ++j) {
            const int col = n0 + wn * 32 + j * 8 + gc2;
            *(float2*)(Cf + (size_t)row * N + col) =
                make_float2(acc[i][j][0], acc[i][j][1]);
            *(float2*)(Cf + (size_t)(row + 8) * N + col) =
                make_float2(acc[i][j][2], acc[i][j][3]);
        }
    }
}

// ---------------------------------------------------------------------------
// Tensor-core flash attention, causal, bf16 3-split (unchanged; validated).
// ---------------------------------------------------------------------------
__global__ __launch_bounds__(256, 2)
void attn_tc(const __nv_bfloat16* __restrict__ qkvh,
             const __nv_bfloat16* __restrict__ qkvl,
             __nv_bfloat16* __restrict__ ahi, __nv_bfloat16* __restrict__ alo)
{
    extern __shared__ __align__(16) char smA[];
    const uint32_t sQ  = smem_u32(smA);
    const uint32_t sKV = sQ + AQBYTES;

    const int tid  = threadIdx.x;
    const int wid  = tid >> 5;
    const int lane = tid & 31;
    const int qb   = (int)gridDim.x - 1 - (int)blockIdx.x;
    const int h    = blockIdx.y;
    const int b    = blockIdx.z;

    const size_t rowQ0 = (size_t)(b * LL + qb * QB);
    const size_t rowB  = (size_t)(b * LL);

#pragma unroll
    for (int i = 0; i < 8; ++i) {
        int s = tid + (i << 8);
        int half = s >> 10;
        int row  = (s >> 3) & 127;
        int u    = s & 7;
        const __nv_bfloat16* src = (half ? qkvl : qkvh)
            + (rowQ0 + row) * (3 * EE) + h * DD + u * 8;
        cp16(sQ + half * 18432 + row * APITCH + u * 16, src);
    }
    auto issue_kv = [&](int kb, uint32_t dst) {
#pragma unroll
        for (int i = 0; i < 8; ++i) {
            int s = tid + (i << 8);
            int tn  = s >> 9;
            int row = (s >> 3) & 63;
            int u   = s & 7;
            const __nv_bfloat16* base = (tn & 1) ? qkvl : qkvh;
            int col = ((tn >> 1) ? 2 * EE : EE) + h * DD + u * 8;
            cp16(dst + tn * AKTILE + row * APITCH + u * 16,
                 base + (rowB + (size_t)kb * KVB + row) * (3 * EE) + col);
        }
    };
    issue_kv(0, sKV);
    cp_commit();
    cp_wait0();
    __syncthreads();

    const int q0   = wid * 16;
    const int qmin = qb * QB + q0;
    const int rA = lane & 15, uA = (lane >> 4);
    const int rT = (lane & 7) + ((lane >> 4) << 3);
    const int uT = (lane >> 3) & 1;

    float m0 = -1e30f, m1 = -1e30f, l0 = 0.f, l1 = 0.f;
    float O[8][4];
#pragma unroll
    for (int j = 0; j < 8; ++j)
#pragma unroll
        for (int v = 0; v < 4; ++v) O[j][v] = 0.f;

    const int nkb = 2 * qb + 2;
    int buf = 0;
    for (int kb = 0; kb < nkb; ++kb) {
        if (kb + 1 < nkb) { issue_kv(kb + 1, sKV + (buf ^ 1) * ASTAGE); cp_commit(); }
        const uint32_t st = sKV + buf * ASTAGE;
        const bool skip = (kb * KVB > qmin + 15);
        if (!skip) {
            float acc[8][4];
#pragma unroll
            for (int j = 0; j < 8; ++j)
#pragma unroll
                for (int v = 0; v < 4; ++v) acc[j][v] = 0.f;

#pragma unroll
            for (int ks = 0; ks < 4; ++ks) {
                uint32_t aH[4], aL[4];
                ldm4(sQ + (q0 + rA) * APITCH + uA * 16 + ks * 32, aH);
                ldm4(sQ + 18432 + (q0 + rA) * APITCH + uA * 16 + ks * 32, aL);
#pragma unroll
                for (int jp = 0; jp < 4; ++jp) {
                    uint32_t bH[4], bL[4];
                    const uint32_t ko = (uint32_t)((jp * 16 + rA) * APITCH + uA * 16 + ks * 32);
                    ldm4(st + ko, bH);
                    mma_bf16(acc[2 * jp],     aH, bH[0], bH[2]);
                    mma_bf16(acc[2 * jp + 1], aH, bH[1], bH[3]);
                    mma_bf16(acc[2 * jp],     aL, bH[0], bH[2]);
                    mma_bf16(acc[2 * jp + 1], aL, bH[1], bH[3]);
                    ldm4(st + AKTILE + ko, bL);
                    mma_bf16(acc[2 * jp],     aH, bL[0], bL[2]);
                    mma_bf16(acc[2 * jp + 1], aH, bL[1], bL[3]);
                }
            }

            const int r0 = qmin + (lane >> 2), r1 = r0 + 8;
            const bool needmask = (kb * KVB + KVB - 1 > qmin);
#pragma unroll
            for (int j = 0; j < 8; ++j) {
                acc[j][0] *= 0.125f; acc[j][1] *= 0.125f;
                acc[j][2] *= 0.125f; acc[j][3] *= 0.125f;
                if (needmask) {
                    const int key = kb * KVB + j * 8 + ((lane & 3) << 1);
                    if (key     > r0) acc[j][0] = -1e30f;
                    if (key + 1 > r0) acc[j][1] = -1e30f;
                    if (key     > r1) acc[j][2] = -1e30f;
                    if (key + 1 > r1) acc[j][3] = -1e30f;
                }
            }

            float mx0 = -1e30f, mx1 = -1e30f;
#pragma unroll
            for (int j = 0; j < 8; ++j) {
                mx0 = fmaxf(mx0, fmaxf(acc[j][0], acc[j][1]));
                mx1 = fmaxf(mx1, fmaxf(acc[j][2], acc[j][3]));
            }
            mx0 = fmaxf(mx0, __shfl_xor_sync(0xffffffffu, mx0, 1));
            mx0 = fmaxf(mx0, __shfl_xor_sync(0xffffffffu, mx0, 2));
            mx1 = fmaxf(mx1, __shfl_xor_sync(0xffffffffu, mx1, 1));
            mx1 = fmaxf(mx1, __shfl_xor_sync(0xffffffffu, mx1, 2));
            const float mn0 = fmaxf(m0, mx0), mn1 = fmaxf(m1, mx1);
            const float c0 = __expf(m0 - mn0), c1 = __expf(m1 - mn1);
            float s0 = 0.f, s1 = 0.f;
#pragma unroll
            for (int j = 0; j < 8; ++j) {
                acc[j][0] = __expf(acc[j][0] - mn0); s0 += acc[j][0];
                acc[j][1] = __expf(acc[j][1] - mn0); s0 += acc[j][1];
                acc[j][2] = __expf(acc[j][2] - mn1); s1 += acc[j][2];
                acc[j][3] = __expf(acc[j][3] - mn1); s1 += acc[j][3];
            }
            s0 += __shfl_xor_sync(0xffffffffu, s0, 1);
            s0 += __shfl_xor_sync(0xffffffffu, s0, 2);
            s1 += __shfl_xor_sync(0xffffffffu, s1, 1);
            s1 += __shfl_xor_sync(0xffffffffu, s1, 2);
            l0 = l0 * c0 + s0; l1 = l1 * c1 + s1;
            m0 = mn0; m1 = mn1;
#pragma unroll
            for (int j = 0; j < 8; ++j) {
                O[j][0] *= c0; O[j][1] *= c0;
                O[j][2] *= c1; O[j][3] *= c1;
            }

#pragma unroll
            for (int t = 0; t < 4; ++t) {
                uint32_t aPh[4], aPl[4];
#pragma unroll
                for (int hf = 0; hf < 2; ++hf) {
                    const float* pv = acc[2 * t + hf];
                    __nv_bfloat16 h0 = __float2bfloat16(pv[0]);
                    __nv_bfloat16 h1 = __float2bfloat16(pv[1]);
                    __nv_bfloat16 h2 = __float2bfloat16(pv[2]);
                    __nv_bfloat16 h3 = __float2bfloat16(pv[3]);
                    aPh[hf * 2]     = pack2bf(h0, h1);
                    aPh[hf * 2 + 1] = pack2bf(h2, h3);
                    aPl[hf * 2]     = pack2bf(
                        __float2bfloat16(pv[0] - __bfloat162float(h0)),
                        __float2bfloat16(pv[1] - __bfloat162float(h1)));
                    aPl[hf * 2 + 1] = pack2bf(
                        __float2bfloat16(pv[2] - __bfloat162float(h2)),
                        __float2bfloat16(pv[3] - __bfloat162float(h3)));
                }
#pragma unroll
                for (int jp = 0; jp < 4; ++jp) {
                    uint32_t vH[4], vL[4];
                    const uint32_t vo = (uint32_t)((t * 16 + rT) * APITCH
                                                   + (jp * 2 + uT) * 16);
                    ldm4t(st + 2 * AKTILE + vo, vH);
                    mma_bf16(O[2 * jp],     aPh, vH[0], vH[2]);
                    mma_bf16(O[2 * jp + 1], aPh, vH[1], vH[3]);
                    mma_bf16(O[2 * jp],     aPl, vH[0], vH[2]);
                    mma_bf16(O[2 * jp + 1], aPl, vH[1], vH[3]);
                    ldm4t(st + 3 * AKTILE + vo, vL);
                    mma_bf16(O[2 * jp],     aPh, vL[0], vL[2]);
                    mma_bf16(O[2 * jp + 1], aPh, vL[1], vL[3]);
                }
            }
        }
        if (kb + 1 < nkb) cp_wait0();
        __syncthreads();
        buf ^= 1;
    }

    const float i0 = 1.f / l0, i1 = 1.f / l1;
    const size_t g0 = (rowQ0 + q0 + (lane >> 2)) * EE + h * DD;
    const size_t g1 = g0 + (size_t)8 * EE;
#pragma unroll
    for (int j = 0; j < 8; ++j) {
        const int col = j * 8 + ((lane & 3) << 1);
#pragma unroll
        for (int rr = 0; rr < 2; ++rr) {
            const float v0 = O[j][rr * 2] * (rr ? i1 : i0);
            const float v1 = O[j][rr * 2 + 1] * (rr ? i1 : i0);
            __nv_bfloat16 h0 = __float2bfloat16(v0);
            __nv_bfloat16 h1 = __float2bfloat16(v1);
            __nv_bfloat16 lo0 = __float2bfloat16(v0 - __bfloat162float(h0));
            __nv_bfloat16 lo1 = __float2bfloat16(v1 - __bfloat162float(h1));
            const size_t off = (rr ? g1 : g0) + col;
            *(uint32_t*)(ahi + off) = pack2bf(h0, h1);
            *(uint32_t*)(alo + off) = pack2bf(lo0, lo1);
        }
    }
}

// ---------------------------------------------------------------------------
extern "C" void kernel_launch(void* const* d_in, const int* in_sizes, int n_in,
                              void* d_out, int out_size)
{
    (void)in_sizes; (void)n_in; (void)out_size;
    const float* net_in = (const float*)d_in[0];
    const float* W_qkv  = (const float*)d_in[1];
    const float* W_out  = (const float*)d_in[2];
    float* outp = (float*)d_out;

    __nv_bfloat16 *xhi, *xlo, *wqhi, *wqlo, *wohi, *wolo, *qh, *ql, *ahi, *alo;
    cudaGetSymbolAddress((void**)&xhi,  g_xhi);
    cudaGetSymbolAddress((void**)&xlo,  g_xlo);
    cudaGetSymbolAddress((void**)&wqhi, g_wqhi);
    cudaGetSymbolAddress((void**)&wqlo, g_wqlo);
    cudaGetSymbolAddress((void**)&wohi, g_wohi);
    cudaGetSymbolAddress((void**)&wolo, g_wolo);
    cudaGetSymbolAddress((void**)&qh,   g_qkvhi);
    cudaGetSymbolAddress((void**)&ql,   g_qkvlo);
    cudaGetSymbolAddress((void**)&ahi,  g_ahi);
    cudaGetSymbolAddress((void**)&alo,  g_alo);

    cudaFuncSetAttribute(gemm3f,
                         cudaFuncAttributeMaxDynamicSharedMemorySize, FSMEM);
    cudaFuncSetAttribute(gemm3x,
                         cudaFuncAttributeMaxDynamicSharedMemorySize, GSMEM);
    cudaFuncSetAttribute(attn_tc,
                         cudaFuncAttributeMaxDynamicSharedMemorySize, ASMEM);

    // 0) input/weight splits
    {
        int n4 = (MM * EE) / 4;
        split_fp32<<<(n4 + 255) / 256, 256>>>(net_in, xhi, xlo, n4);
        n4 = (3 * EE * EE) / 4;
        split_fp32<<<(n4 + 255) / 256, 256>>>(W_qkv, wqhi, wqlo, n4);
        n4 = (EE * EE) / 4;
        split_fp32<<<(n4 + 255) / 256, 256>>>(W_out, wohi, wolo, n4);
    }

    // 1) QKV projection (big GEMM, >=5 waves) -> gemm3f -> split-bf16 qkv
    dim3 g1((3 * EE) / 64, MM / 128);          // 48 x 32
    gemm3f<<<g1, 256, FSMEM>>>(xhi, xlo, wqhi, wqlo, qh, ql, 3 * EE);

    // 2) Tensor-core causal flash attention -> split-bf16 activations
    dim3 ga(LL / QB, HH, BB);
    attn_tc<<<ga, 256, ASMEM>>>(qh, ql, ahi, alo);

    // 3) Output projection (small GEMM, <1 wave) -> gemm3x -> fp32 d_out
    dim3 g3(EE / 128, MM / 128);               // 8 x 32
    gemm3x<<<g3, 256, GSMEM>>>(ahi, alo, wohi, wolo, outp, EE);
}